// round 6
// baseline (speedup 1.0000x reference)
#include <cuda_runtime.h>
#include <cuda_fp16.h>

static constexpr int NB  = 64;     // batch
static constexpr int PP  = 196;    // spatial positions
static constexpr int EE  = 2048;   // feature dim
static constexpr int DD  = 256;    // hidden
static constexpr int HH  = 256;    // attention hidden
static constexpr int EMB = 256;    // embedding
static constexpr int VV  = 10000;  // vocab
static constexpr int LL  = 32;     // caption length
static constexpr int TT  = 31;     // timesteps
static constexpr int XK  = EMB + EE + DD;  // 2560
static constexpr int G4  = 4 * DD;         // 1024
static constexpr int KC  = 10;             // split-K chunks for gates gemm

__device__ int    g_order[NB];
__device__ int    g_target[NB];
__device__ __half g_feat16[NB * PP * EE];   // 51.4 MB fp16 feat, order-permuted
__device__ __half g_fe16[NB * PP * HH];     // 6.4 MB fp16 attention features
__device__ float  g_mean[NB * EE];
__device__ float  g_h[NB * DD];
__device__ float  g_c[NB * DD];
__device__ float  g_score[NB * PP];
__device__ float  g_x[NB * XK];
__device__ float  g_gp[KC * NB * G4];       // split-K partials (gates / init)
__device__ float  g_gatep[2 * NB * EE];     // split-K partials for gate pre-act
__device__ __half g_Wg16[DD * EE];          // W_gate fp16
__device__ __half g_Wih16[XK * G4];         // [W_ih ; W_hh] fp16 concat
__device__ __half g_Whead16[DD * VV];       // W_head fp16

__device__ __forceinline__ float sigf(float x) { return 1.0f / (1.0f + expf(-x)); }

// ---------------------------------------------------------------------------
// K0: stable descending counting sort of lengths (matches jnp.argsort(-len))
// ---------------------------------------------------------------------------
__global__ void k_order(const int* __restrict__ caplen) {
    if (threadIdx.x == 0) {
        int idx = 0;
        for (int v = LL; v >= 1; --v) {
            for (int i = 0; i < NB; ++i) {
                if (caplen[i] == v) {
                    g_order[idx]  = i;
                    g_target[idx] = v - 1;
                    ++idx;
                }
            }
        }
    }
}

// ---------------------------------------------------------------------------
// K_cvt: one-time fp32 -> fp16 conversion of step-loop weights
// ---------------------------------------------------------------------------
__global__ void k_cvt(const float* __restrict__ Wg, const float* __restrict__ Wih,
                      const float* __restrict__ Whh, const float* __restrict__ Whead) {
    const int NQ_G  = (DD * EE) / 4;
    const int NQ_IH = (2304 * G4) / 4;
    const int NQ_HH = (DD * G4) / 4;
    const int NQ_HD = (DD * VV) / 4;
    const int total = NQ_G + NQ_IH + NQ_HH + NQ_HD;
    for (int i = blockIdx.x * blockDim.x + threadIdx.x; i < total;
         i += gridDim.x * blockDim.x) {
        const float* src; __half* dst; int q;
        if (i < NQ_G)                    { src = Wg;    dst = g_Wg16;              q = i; }
        else if (i < NQ_G + NQ_IH)       { src = Wih;   dst = g_Wih16;             q = i - NQ_G; }
        else if (i < NQ_G + NQ_IH + NQ_HH){ src = Whh;  dst = g_Wih16 + 2304 * G4; q = i - NQ_G - NQ_IH; }
        else                             { src = Whead; dst = g_Whead16;           q = i - NQ_G - NQ_IH - NQ_HH; }
        float4 v = *(const float4*)(src + (size_t)q * 4);
        *(__half2*)(dst + (size_t)q * 4)     = __floats2half2_rn(v.x, v.y);
        *(__half2*)(dst + (size_t)q * 4 + 2) = __floats2half2_rn(v.z, v.w);
    }
}

// ---------------------------------------------------------------------------
// K_cvtf: one-time feat -> fp16 with the order permutation baked in.
// grid NB*PP blocks (one per output row), 256 threads, 8 elems/thread.
// ---------------------------------------------------------------------------
__global__ void __launch_bounds__(256) k_cvtf(const float* __restrict__ feat) {
    int row = blockIdx.x;                // b*PP + p (sorted order)
    int b = row / PP, p = row % PP;
    const float* src = feat + ((size_t)g_order[b] * PP + p) * EE + threadIdx.x * 8;
    __half* dst = g_feat16 + (size_t)row * EE + threadIdx.x * 8;
    float4 v0 = *(const float4*)(src);
    float4 v1 = *(const float4*)(src + 4);
    *(__half2*)(dst + 0) = __floats2half2_rn(v0.x, v0.y);
    *(__half2*)(dst + 2) = __floats2half2_rn(v0.z, v0.w);
    *(__half2*)(dst + 4) = __floats2half2_rn(v1.x, v1.y);
    *(__half2*)(dst + 6) = __floats2half2_rn(v1.z, v1.w);
}

// ---------------------------------------------------------------------------
// K3: fused launch, grid (98, 5):
//   blockIdx.y < 4 : fe = feat16 @ Wf + bf -> fp16. BM=128 BN=64 BK=16.
//   blockIdx.y == 4: mean over positions from fp32 feat (blocks 0..63)
// ---------------------------------------------------------------------------
__global__ void __launch_bounds__(256) k_fe(const float* __restrict__ feat,
                                            const float* __restrict__ Wf,
                                            const float* __restrict__ bf) {
    int tid = threadIdx.x;
    int mb = blockIdx.x, nb = blockIdx.y;

    if (nb == 4) {
        if (mb >= NB) return;
        int b = mb;
        const float4* base = (const float4*)(feat + (size_t)g_order[b] * PP * EE);
        float4 sA = make_float4(0.f, 0.f, 0.f, 0.f);
        float4 sB = make_float4(0.f, 0.f, 0.f, 0.f);
        #pragma unroll 2
        for (int p = 0; p < PP; ++p) {
            float4 v0 = __ldcs(base + (size_t)p * (EE / 4) + tid);
            float4 v1 = __ldcs(base + (size_t)p * (EE / 4) + tid + 256);
            sA.x += v0.x; sA.y += v0.y; sA.z += v0.z; sA.w += v0.w;
            sB.x += v1.x; sB.y += v1.y; sB.z += v1.z; sB.w += v1.w;
        }
        const float inv = 1.0f / PP;
        sA.x *= inv; sA.y *= inv; sA.z *= inv; sA.w *= inv;
        sB.x *= inv; sB.y *= inv; sB.z *= inv; sB.w *= inv;
        *(float4*)(g_mean + b * EE + tid * 4)        = sA;
        *(float4*)(g_mean + b * EE + 1024 + tid * 4) = sB;
        return;
    }

    __shared__ float As[16][132];
    __shared__ float Bs[16][64];

    float acc[8][4] = {};
    int rb = (tid >> 4) * 8, cb = (tid & 15) * 4;

    int ar = tid >> 1, ak = (tid & 1) * 8;
    int bk = tid >> 4, bn = (tid & 15) * 4;
    const __half* arow = g_feat16 + (size_t)(mb * 128 + ar) * EE;

    for (int k0 = 0; k0 < EE; k0 += 16) {
        {
            uint4 raw = *(const uint4*)(arow + k0 + ak);
            float2 f0 = __half22float2(*reinterpret_cast<__half2*>(&raw.x));
            float2 f1 = __half22float2(*reinterpret_cast<__half2*>(&raw.y));
            float2 f2 = __half22float2(*reinterpret_cast<__half2*>(&raw.z));
            float2 f3 = __half22float2(*reinterpret_cast<__half2*>(&raw.w));
            As[ak + 0][ar] = f0.x; As[ak + 1][ar] = f0.y;
            As[ak + 2][ar] = f1.x; As[ak + 3][ar] = f1.y;
            As[ak + 4][ar] = f2.x; As[ak + 5][ar] = f2.y;
            As[ak + 6][ar] = f3.x; As[ak + 7][ar] = f3.y;
        }
        {
            *(float4*)&Bs[bk][bn] = *(const float4*)(Wf + (size_t)(k0 + bk) * HH + nb * 64 + bn);
        }
        __syncthreads();
        #pragma unroll
        for (int kk = 0; kk < 16; ++kk) {
            float a[8], bv[4];
            *(float4*)(a)     = *(float4*)&As[kk][rb];
            *(float4*)(a + 4) = *(float4*)&As[kk][rb + 4];
            *(float4*)(bv)    = *(float4*)&Bs[kk][cb];
            #pragma unroll
            for (int i = 0; i < 8; ++i)
                #pragma unroll
                for (int j = 0; j < 4; ++j) acc[i][j] += a[i] * bv[j];
        }
        __syncthreads();
    }
    #pragma unroll
    for (int i = 0; i < 8; ++i) {
        int gm = mb * 128 + rb + i;
        int gn = nb * 64 + cb;
        __half2 h01 = __floats2half2_rn(acc[i][0] + bf[gn + 0], acc[i][1] + bf[gn + 1]);
        __half2 h23 = __floats2half2_rn(acc[i][2] + bf[gn + 2], acc[i][3] + bf[gn + 3]);
        *(__half2*)(g_fe16 + (size_t)gm * HH + gn)     = h01;
        *(__half2*)(g_fe16 + (size_t)gm * HH + gn + 2) = h23;
    }
}

// ---------------------------------------------------------------------------
// K2a: init GEMM  mean(64x2048) @ [W_hid | W_cell](2048x512), split-K=8.
// grid (8 nb, 8 kc): nb<4 -> W_hid cols, nb>=4 -> W_cell cols.
// Partials into g_gp with row stride 512.
// ---------------------------------------------------------------------------
__global__ void __launch_bounds__(256) k_initA(const float* __restrict__ W_hid,
                                               const float* __restrict__ W_cell) {
    __shared__ float As[16][68];
    __shared__ float Bs[16][64];
    int tid = threadIdx.x;
    int nb = blockIdx.x, kc = blockIdx.y;
    const float* wsrc = (nb < 4) ? W_hid : W_cell;
    int ncol0 = (nb & 3) * 64;
    int k0g = kc * 256;
    float acc[4][4] = {};
    int rb = (tid >> 4) * 4, cb = (tid & 15) * 4;

    for (int kt = 0; kt < 256; kt += 16) {
        {
            int r = tid >> 2, kk = (tid & 3) * 4;
            float4 av = *(const float4*)(g_mean + r * EE + k0g + kt + kk);
            As[kk + 0][r] = av.x; As[kk + 1][r] = av.y;
            As[kk + 2][r] = av.z; As[kk + 3][r] = av.w;
        }
        {
            int kk = tid >> 4, n = (tid & 15) * 4;
            *(float4*)&Bs[kk][n] =
                *(const float4*)(wsrc + (size_t)(k0g + kt + kk) * DD + ncol0 + n);
        }
        __syncthreads();
        #pragma unroll
        for (int kk = 0; kk < 16; ++kk) {
            float a[4], bv[4];
            *(float4*)a  = *(float4*)&As[kk][rb];
            *(float4*)bv = *(float4*)&Bs[kk][cb];
            #pragma unroll
            for (int i = 0; i < 4; ++i)
                #pragma unroll
                for (int j = 0; j < 4; ++j) acc[i][j] += a[i] * bv[j];
        }
        __syncthreads();
    }
    #pragma unroll
    for (int i = 0; i < 4; ++i)
        #pragma unroll
        for (int j = 0; j < 4; ++j)
            g_gp[((size_t)kc * NB + rb + i) * 512 + nb * 64 + cb + j] = acc[i][j];
}

// K2b: reduce init partials + biases -> h0, c0
__global__ void k_init2(const float* __restrict__ b_hid, const float* __restrict__ b_cell) {
    int b = blockIdx.x, j = threadIdx.x;
    float h = b_hid[j], c = b_cell[j];
    #pragma unroll
    for (int kc = 0; kc < 8; ++kc) {
        const float* p = g_gp + ((size_t)kc * NB + b) * 512;
        h += p[j];
        c += p[256 + j];
    }
    g_h[b * DD + j] = h;
    g_c[b * DD + j] = c;
}

// ---------------------------------------------------------------------------
// K4 (per step): ONE launch, three independent jobs:
//   blocks [0,128):   attention scores (2 blocks per batch row, 98 p each)
//   blocks [128,192): gate-pre GEMM h @ W_gate16, split-K=2
//   blocks [192,349): head GEMM for step t-1 with W_head16
// ---------------------------------------------------------------------------
__global__ void __launch_bounds__(256) k_stepA(
        const float* __restrict__ Wh, const float* __restrict__ bh,
        const float* __restrict__ We, const float* __restrict__ be,
        const float* __restrict__ b_head,
        int t, float* __restrict__ out) {
    int tid = threadIdx.x;
    if (blockIdx.x < 2 * NB) {
        int b = blockIdx.x >> 1, half = blockIdx.x & 1;
        int lane = tid & 31, wid = tid >> 5;
        __shared__ float sh[DD], she[HH], swe[HH];

        sh[tid] = g_h[b * DD + tid];
        swe[tid] = We[tid];
        __syncthreads();

        float acc = bh[tid];
        #pragma unroll 8
        for (int k = 0; k < DD; ++k) acc += sh[k] * Wh[k * HH + tid];
        she[tid] = acc;
        __syncthreads();

        float be0 = be[0];
        int p0 = half * 98, p1 = p0 + 98;
        const __half* febase = g_fe16 + (size_t)b * PP * HH;
        for (int p = p0 + wid; p < p1; p += 8) {
            const __half* fr = febase + (size_t)p * HH;
            float s = 0.f;
            #pragma unroll
            for (int it = 0; it < 4; ++it) {
                int j = it * 64 + lane * 2;
                float2 fv = __half22float2(*(const __half2*)(fr + j));
                float v0 = fv.x + she[j], v1 = fv.y + she[j + 1];
                s += fmaxf(v0, 0.f) * swe[j] + fmaxf(v1, 0.f) * swe[j + 1];
            }
            #pragma unroll
            for (int o = 16; o; o >>= 1) s += __shfl_xor_sync(0xffffffffu, s, o);
            if (lane == 0) g_score[b * PP + p] = s + be0;
        }
    } else if (blockIdx.x < 3 * NB) {
        __shared__ float As[16][68];
        __shared__ float Bs[16][64];
        int bid = blockIdx.x - 2 * NB;
        int nb = bid & 31, kc = bid >> 5;
        int kbase = kc * 128;
        float acc[4][4] = {};
        int rb = (tid >> 4) * 4, cb = (tid & 15) * 4;

        for (int kt = 0; kt < 128; kt += 16) {
            {
                int r = tid >> 2, kk = (tid & 3) * 4;
                float4 av = *(const float4*)(g_h + r * DD + kbase + kt + kk);
                As[kk + 0][r] = av.x; As[kk + 1][r] = av.y;
                As[kk + 2][r] = av.z; As[kk + 3][r] = av.w;
            }
            {
                int kk = tid >> 4, n = (tid & 15) * 4;
                const __half* src = g_Wg16 + (size_t)(kbase + kt + kk) * EE + nb * 64 + n;
                float2 f0 = __half22float2(*(const __half2*)(src));
                float2 f1 = __half22float2(*(const __half2*)(src + 2));
                Bs[kk][n + 0] = f0.x; Bs[kk][n + 1] = f0.y;
                Bs[kk][n + 2] = f1.x; Bs[kk][n + 3] = f1.y;
            }
            __syncthreads();
            #pragma unroll
            for (int kk = 0; kk < 16; ++kk) {
                float a[4], bv[4];
                *(float4*)a  = *(float4*)&As[kk][rb];
                *(float4*)bv = *(float4*)&Bs[kk][cb];
                #pragma unroll
                for (int i = 0; i < 4; ++i)
                    #pragma unroll
                    for (int j = 0; j < 4; ++j) acc[i][j] += a[i] * bv[j];
            }
            __syncthreads();
        }
        #pragma unroll
        for (int i = 0; i < 4; ++i)
            #pragma unroll
            for (int j = 0; j < 4; ++j)
                g_gatep[((size_t)kc * NB + rb + i) * EE + nb * 64 + cb + j] = acc[i][j];
    } else {
        int tprev = t - 1;
        __shared__ float As[16][68];
        __shared__ float Bs[16][64];
        int nb = blockIdx.x - 3 * NB;
        int n0 = nb * 64;
        float acc[4][4] = {};
        int rb = (tid >> 4) * 4, cb = (tid & 15) * 4;

        for (int k0 = 0; k0 < DD; k0 += 16) {
            {
                int r = tid >> 2, kk = (tid & 3) * 4;
                float4 av = *(const float4*)(g_h + r * DD + k0 + kk);
                As[kk + 0][r] = av.x; As[kk + 1][r] = av.y;
                As[kk + 2][r] = av.z; As[kk + 3][r] = av.w;
            }
            {
                int kk = tid >> 4, n = (tid & 15) * 4;
                int gn = n0 + n;
                const __half* src = g_Whead16 + (size_t)(k0 + kk) * VV + gn;
                float b0, b1, b2, b3;
                if (gn + 3 < VV) {
                    float2 f0 = __half22float2(*(const __half2*)(src));
                    float2 f1 = __half22float2(*(const __half2*)(src + 2));
                    b0 = f0.x; b1 = f0.y; b2 = f1.x; b3 = f1.y;
                } else {
                    b0 = (gn + 0 < VV) ? __half2float(src[0]) : 0.f;
                    b1 = (gn + 1 < VV) ? __half2float(src[1]) : 0.f;
                    b2 = (gn + 2 < VV) ? __half2float(src[2]) : 0.f;
                    b3 = (gn + 3 < VV) ? __half2float(src[3]) : 0.f;
                }
                Bs[kk][n + 0] = b0; Bs[kk][n + 1] = b1;
                Bs[kk][n + 2] = b2; Bs[kk][n + 3] = b3;
            }
            __syncthreads();
            #pragma unroll
            for (int kk = 0; kk < 16; ++kk) {
                float a[4], bv[4];
                *(float4*)a  = *(float4*)&As[kk][rb];
                *(float4*)bv = *(float4*)&Bs[kk][cb];
                #pragma unroll
                for (int i = 0; i < 4; ++i)
                    #pragma unroll
                    for (int j = 0; j < 4; ++j) acc[i][j] += a[i] * bv[j];
            }
            __syncthreads();
        }
        #pragma unroll
        for (int i = 0; i < 4; ++i) {
            int b = rb + i;
            bool msk = (g_target[b] > tprev);
            size_t rowbase = ((size_t)b * TT + tprev) * VV;
            #pragma unroll
            for (int j = 0; j < 4; ++j) {
                int gn = n0 + cb + j;
                if (gn < VV) out[rowbase + gn] = msk ? (acc[i][j] + b_head[gn]) : 0.f;
            }
        }
    }
}

// ---------------------------------------------------------------------------
// K6 (per step): softmax(scores) + fp16 ctx scan + assemble x. grid (NB,4), 128.
// ---------------------------------------------------------------------------
__global__ void __launch_bounds__(128) k_ctx(
        const float* __restrict__ b_gate,
        const float* __restrict__ emb, const int* __restrict__ tok, int t,
        float* __restrict__ out_att) {
    int b = blockIdx.x, tid = threadIdx.x;
    int lane = tid & 31, wid = tid >> 5;
    __shared__ float sw[PP];
    __shared__ float red[4];

    // ---- softmax over 196 scores ----
    float v0 = g_score[b * PP + tid];
    float v1 = (tid + 128 < PP) ? g_score[b * PP + tid + 128] : -3.4e38f;
    float m = fmaxf(v0, v1);
    #pragma unroll
    for (int o = 16; o; o >>= 1) m = fmaxf(m, __shfl_xor_sync(0xffffffffu, m, o));
    if (lane == 0) red[wid] = m;
    __syncthreads();
    if (tid == 0) red[0] = fmaxf(fmaxf(red[0], red[1]), fmaxf(red[2], red[3]));
    __syncthreads();
    float mx = red[0];
    __syncthreads();

    float e0 = expf(v0 - mx);
    float e1 = (tid + 128 < PP) ? expf(v1 - mx) : 0.f;
    float s = e0 + e1;
    #pragma unroll
    for (int o = 16; o; o >>= 1) s += __shfl_xor_sync(0xffffffffu, s, o);
    if (lane == 0) red[wid] = s;
    __syncthreads();
    if (tid == 0) red[0] = (red[0] + red[1]) + (red[2] + red[3]);
    __syncthreads();
    float inv = 1.0f / red[0];
    sw[tid] = e0 * inv;
    if (tid + 128 < PP) sw[tid + 128] = e1 * inv;
    __syncthreads();

    if (blockIdx.y == 0) {
        bool msk = (g_target[b] > t);
        out_att[((size_t)b * TT + t) * PP + tid] = msk ? sw[tid] : 0.f;
        if (tid + 128 < PP)
            out_att[((size_t)b * TT + t) * PP + tid + 128] = msk ? sw[tid + 128] : 0.f;
    }

    // ---- ctx scan over fp16 feat (order already baked in) ----
    int e0i = blockIdx.y * 512 + tid * 4;
    const __half* fb = g_feat16 + (size_t)b * PP * EE + e0i;

    float4 s0 = make_float4(0.f, 0.f, 0.f, 0.f);
    float4 s1 = make_float4(0.f, 0.f, 0.f, 0.f);
    float4 s2 = make_float4(0.f, 0.f, 0.f, 0.f);
    float4 s3 = make_float4(0.f, 0.f, 0.f, 0.f);
    for (int p = 0; p < PP; p += 4) {
        float w0 = sw[p], w1 = sw[p + 1], w2 = sw[p + 2], w3 = sw[p + 3];
        uint2 r0 = __ldcs((const uint2*)(fb + (size_t)(p + 0) * EE));
        uint2 r1 = __ldcs((const uint2*)(fb + (size_t)(p + 1) * EE));
        uint2 r2 = __ldcs((const uint2*)(fb + (size_t)(p + 2) * EE));
        uint2 r3 = __ldcs((const uint2*)(fb + (size_t)(p + 3) * EE));
        float2 a0 = __half22float2(*reinterpret_cast<__half2*>(&r0.x));
        float2 b0 = __half22float2(*reinterpret_cast<__half2*>(&r0.y));
        float2 a1 = __half22float2(*reinterpret_cast<__half2*>(&r1.x));
        float2 b1 = __half22float2(*reinterpret_cast<__half2*>(&r1.y));
        float2 a2 = __half22float2(*reinterpret_cast<__half2*>(&r2.x));
        float2 b2 = __half22float2(*reinterpret_cast<__half2*>(&r2.y));
        float2 a3 = __half22float2(*reinterpret_cast<__half2*>(&r3.x));
        float2 b3 = __half22float2(*reinterpret_cast<__half2*>(&r3.y));
        s0.x += w0 * a0.x; s0.y += w0 * a0.y; s0.z += w0 * b0.x; s0.w += w0 * b0.y;
        s1.x += w1 * a1.x; s1.y += w1 * a1.y; s1.z += w1 * b1.x; s1.w += w1 * b1.y;
        s2.x += w2 * a2.x; s2.y += w2 * a2.y; s2.z += w2 * b2.x; s2.w += w2 * b2.y;
        s3.x += w3 * a3.x; s3.y += w3 * a3.y; s3.z += w3 * b3.x; s3.w += w3 * b3.y;
    }
    float4 sum;
    sum.x = (s0.x + s1.x) + (s2.x + s3.x);
    sum.y = (s0.y + s1.y) + (s2.y + s3.y);
    sum.z = (s0.z + s1.z) + (s2.z + s3.z);
    sum.w = (s0.w + s1.w) + (s2.w + s3.w);

    float4 gp0 = *(const float4*)(g_gatep + (size_t)b * EE + e0i);
    float4 gp1 = *(const float4*)(g_gatep + ((size_t)NB + b) * EE + e0i);
    float4 bg  = *(const float4*)(b_gate + e0i);
    float4 ctx;
    ctx.x = sum.x * sigf(bg.x + gp0.x + gp1.x);
    ctx.y = sum.y * sigf(bg.y + gp0.y + gp1.y);
    ctx.z = sum.z * sigf(bg.z + gp0.z + gp1.z);
    ctx.w = sum.w * sigf(bg.w + gp0.w + gp1.w);
    *(float4*)(g_x + (size_t)b * XK + EMB + e0i) = ctx;

    if (blockIdx.y == 0) {
        int token = tok[g_order[b] * LL + t];
        g_x[b * XK + tid] = emb[(size_t)token * EMB + tid];
        g_x[b * XK + tid + 128] = emb[(size_t)token * EMB + tid + 128];
        g_x[b * XK + EMB + EE + tid] = g_h[b * DD + tid];
        g_x[b * XK + EMB + EE + tid + 128] = g_h[b * DD + tid + 128];
    }
}

// ---------------------------------------------------------------------------
// K7 (per step): gates GEMM  x(64x2560) @ [W_ih;W_hh]16(2560x1024), split-K=10.
// ---------------------------------------------------------------------------
__global__ void k_gates() {
    __shared__ float As[16][68];
    __shared__ float Bs[16][64];
    int tid = threadIdx.x;
    int nb = blockIdx.x, kc = blockIdx.y;
    int k0g = kc * 256;
    const __half* wbase = g_Wih16 + (size_t)k0g * G4;
    float acc[4][4] = {};
    int rb = (tid >> 4) * 4, cb = (tid & 15) * 4;

    for (int kt = 0; kt < 256; kt += 16) {
        {
            int r = tid >> 2, kk = (tid & 3) * 4;
            float4 av = *(const float4*)(g_x + r * XK + k0g + kt + kk);
            As[kk + 0][r] = av.x; As[kk + 1][r] = av.y;
            As[kk + 2][r] = av.z; As[kk + 3][r] = av.w;
        }
        {
            int kk = tid >> 4, n = (tid & 15) * 4;
            const __half* src = wbase + (size_t)(kt + kk) * G4 + nb * 64 + n;
            float2 f0 = __half22float2(*(const __half2*)(src));
            float2 f1 = __half22float2(*(const __half2*)(src + 2));
            Bs[kk][n + 0] = f0.x; Bs[kk][n + 1] = f0.y;
            Bs[kk][n + 2] = f1.x; Bs[kk][n + 3] = f1.y;
        }
        __syncthreads();
        #pragma unroll
        for (int kk = 0; kk < 16; ++kk) {
            float a[4], bv[4];
            *(float4*)a  = *(float4*)&As[kk][rb];
            *(float4*)bv = *(float4*)&Bs[kk][cb];
            #pragma unroll
            for (int i = 0; i < 4; ++i)
                #pragma unroll
                for (int j = 0; j < 4; ++j) acc[i][j] += a[i] * bv[j];
        }
        __syncthreads();
    }
    #pragma unroll
    for (int i = 0; i < 4; ++i)
        #pragma unroll
        for (int j = 0; j < 4; ++j)
            g_gp[((size_t)kc * NB + rb + i) * G4 + nb * 64 + cb + j] = acc[i][j];
}

// ---------------------------------------------------------------------------
// K8 (per step): LSTM pointwise (sums split-K partials + biases; masked update)
// ---------------------------------------------------------------------------
__global__ void k_lstm(const float* __restrict__ b_ih, const float* __restrict__ b_hh, int t) {
    int b = blockIdx.x, j = threadIdx.x;
    float gi = b_ih[j] + b_hh[j];
    float gf = b_ih[DD + j] + b_hh[DD + j];
    float gg = b_ih[2 * DD + j] + b_hh[2 * DD + j];
    float go = b_ih[3 * DD + j] + b_hh[3 * DD + j];
    #pragma unroll
    for (int kc = 0; kc < KC; ++kc) {
        const float* p = g_gp + ((size_t)kc * NB + b) * G4;
        gi += p[j];
        gf += p[DD + j];
        gg += p[2 * DD + j];
        go += p[3 * DD + j];
    }
    float c = g_c[b * DD + j];
    float cn = sigf(gf) * c + sigf(gi) * tanhf(gg);
    float hn = sigf(go) * tanhf(cn);
    if (g_target[b] > t) {
        g_h[b * DD + j] = hn;
        g_c[b * DD + j] = cn;
    }
}

// ---------------------------------------------------------------------------
// K9: standalone head GEMM (only final step t = TT-1), fp16 weights
// ---------------------------------------------------------------------------
__global__ void __launch_bounds__(256) k_head(
        const float* __restrict__ b_head, int t, float* __restrict__ out) {
    __shared__ float As[16][68];
    __shared__ float Bs[16][64];
    int tid = threadIdx.x, nb = blockIdx.x;
    int n0 = nb * 64;
    float acc[4][4] = {};
    int rb = (tid >> 4) * 4, cb = (tid & 15) * 4;

    for (int k0 = 0; k0 < DD; k0 += 16) {
        {
            int r = tid >> 2, kk = (tid & 3) * 4;
            float4 av = *(const float4*)(g_h + r * DD + k0 + kk);
            As[kk + 0][r] = av.x; As[kk + 1][r] = av.y;
            As[kk + 2][r] = av.z; As[kk + 3][r] = av.w;
        }
        {
            int kk = tid >> 4, n = (tid & 15) * 4;
            int gn = n0 + n;
            const __half* src = g_Whead16 + (size_t)(k0 + kk) * VV + gn;
            float b0, b1, b2, b3;
            if (gn + 3 < VV) {
                float2 f0 = __half22float2(*(const __half2*)(src));
                float2 f1 = __half22float2(*(const __half2*)(src + 2));
                b0 = f0.x; b1 = f0.y; b2 = f1.x; b3 = f1.y;
            } else {
                b0 = (gn + 0 < VV) ? __half2float(src[0]) : 0.f;
                b1 = (gn + 1 < VV) ? __half2float(src[1]) : 0.f;
                b2 = (gn + 2 < VV) ? __half2float(src[2]) : 0.f;
                b3 = (gn + 3 < VV) ? __half2float(src[3]) : 0.f;
            }
            Bs[kk][n + 0] = b0; Bs[kk][n + 1] = b1;
            Bs[kk][n + 2] = b2; Bs[kk][n + 3] = b3;
        }
        __syncthreads();
        #pragma unroll
        for (int kk = 0; kk < 16; ++kk) {
            float a[4], bv[4];
            *(float4*)a  = *(float4*)&As[kk][rb];
            *(float4*)bv = *(float4*)&Bs[kk][cb];
            #pragma unroll
            for (int i = 0; i < 4; ++i)
                #pragma unroll
                for (int j = 0; j < 4; ++j) acc[i][j] += a[i] * bv[j];
        }
        __syncthreads();
    }
    #pragma unroll
    for (int i = 0; i < 4; ++i) {
        int b = rb + i;
        bool msk = (g_target[b] > t);
        size_t rowbase = ((size_t)b * TT + t) * VV;
        #pragma unroll
        for (int j = 0; j < 4; ++j) {
            int gn = n0 + cb + j;
            if (gn < VV) out[rowbase + gn] = msk ? (acc[i][j] + b_head[gn]) : 0.f;
        }
    }
}

// ---------------------------------------------------------------------------
extern "C" void kernel_launch(void* const* d_in, const int* in_sizes, int n_in,
                              void* d_out, int out_size) {
    const float* feat   = (const float*)d_in[0];
    const int*   tok    = (const int*)d_in[1];
    const int*   caplen = (const int*)d_in[2];
    const float* Wf     = (const float*)d_in[3];
    const float* bf     = (const float*)d_in[4];
    const float* Wh     = (const float*)d_in[5];
    const float* bh     = (const float*)d_in[6];
    const float* We     = (const float*)d_in[7];
    const float* be     = (const float*)d_in[8];
    const float* emb    = (const float*)d_in[9];
    const float* W_ih   = (const float*)d_in[10];
    const float* b_ih   = (const float*)d_in[11];
    const float* W_hh   = (const float*)d_in[12];
    const float* b_hh   = (const float*)d_in[13];
    const float* W_hid  = (const float*)d_in[14];
    const float* b_hid  = (const float*)d_in[15];
    const float* W_cell = (const float*)d_in[16];
    const float* b_cell = (const float*)d_in[17];
    const float* W_gate = (const float*)d_in[18];
    const float* b_gate = (const float*)d_in[19];
    const float* W_head = (const float*)d_in[20];
    const float* b_head = (const float*)d_in[21];

    float* out = (float*)d_out;
    float* out_att = out + (size_t)NB * TT * VV;

    k_order<<<1, 32>>>(caplen);
    k_cvt<<<512, 256>>>(W_gate, W_ih, W_hh, W_head);
    k_cvtf<<<NB * PP, 256>>>(feat);
    k_fe<<<dim3(98, 5), 256>>>(feat, Wf, bf);     // fe GEMM (fp16 A/out) + mean
    k_initA<<<dim3(8, 8), 256>>>(W_hid, W_cell);  // init GEMM, split-K
    k_init2<<<NB, 256>>>(b_hid, b_cell);

    for (int t = 0; t < TT; ++t) {
        // scores(t) + gpre(t) + head(t-1) in one launch (t=0: no head blocks)
        int nblk = (t == 0) ? 3 * NB : 3 * NB + 157;
        k_stepA<<<nblk, 256>>>(Wh, bh, We, be, b_head, t, out);
        k_ctx<<<dim3(NB, 4), 128>>>(b_gate, emb, tok, t, out_att);
        k_gates<<<dim3(16, 10), 256>>>();
        k_lstm<<<NB, 256>>>(b_ih, b_hh, t);
    }
    k_head<<<157, 256>>>(b_head, TT - 1, out);
}

// round 7
// speedup vs baseline: 1.1687x; 1.1687x over previous
#include <cuda_runtime.h>
#include <cuda_fp16.h>

static constexpr int NB  = 64;     // batch
static constexpr int PP  = 196;    // spatial positions
static constexpr int EE  = 2048;   // feature dim
static constexpr int DD  = 256;    // hidden
static constexpr int HH  = 256;    // attention hidden
static constexpr int EMB = 256;    // embedding
static constexpr int VV  = 10000;  // vocab
static constexpr int LL  = 32;     // caption length
static constexpr int TT  = 31;     // timesteps
static constexpr int XK  = EMB + EE + DD;  // 2560
static constexpr int G4  = 4 * DD;         // 1024
static constexpr int KC  = 10;             // split-K chunks for gates gemm
static constexpr int NBLK = 256;           // persistent grid size

__device__ int    g_order[NB];
__device__ int    g_target[NB];
__device__ __half g_feat16[NB * PP * EE];   // 51.4 MB fp16 feat, order-permuted
__device__ __half g_fe16[NB * PP * HH];     // 6.4 MB fp16 attention features
__device__ float  g_mean[NB * EE];
__device__ float  g_h[NB * DD];
__device__ float  g_c[NB * DD];
__device__ float  g_score[NB * PP];
__device__ float  g_x[NB * XK];
__device__ float  g_gp[KC * NB * G4];       // split-K partials (gates / init)
__device__ float  g_gatep[2 * NB * EE];     // split-K partials for gate pre-act
__device__ __half g_Wg16[DD * EE];          // W_gate fp16
__device__ __half g_Wih16[XK * G4];         // [W_ih ; W_hh] fp16 concat
__device__ __half g_Whead16[DD * VV];       // W_head fp16

// software grid barrier state (count always returns to 0; gen monotonic)
__device__ int          g_bar_count;
__device__ volatile int g_bar_gen;

__device__ __forceinline__ float sigf(float x) { return 1.0f / (1.0f + expf(-x)); }

// ---------------------------------------------------------------------------
// K0: stable descending counting sort of lengths (matches jnp.argsort(-len))
// ---------------------------------------------------------------------------
__global__ void k_order(const int* __restrict__ caplen) {
    if (threadIdx.x == 0) {
        int idx = 0;
        for (int v = LL; v >= 1; --v) {
            for (int i = 0; i < NB; ++i) {
                if (caplen[i] == v) {
                    g_order[idx]  = i;
                    g_target[idx] = v - 1;
                    ++idx;
                }
            }
        }
    }
}

// ---------------------------------------------------------------------------
// K_cvt: one-time fp32 -> fp16 conversion of step-loop weights
// ---------------------------------------------------------------------------
__global__ void k_cvt(const float* __restrict__ Wg, const float* __restrict__ Wih,
                      const float* __restrict__ Whh, const float* __restrict__ Whead) {
    const int NQ_G  = (DD * EE) / 4;
    const int NQ_IH = (2304 * G4) / 4;
    const int NQ_HH = (DD * G4) / 4;
    const int NQ_HD = (DD * VV) / 4;
    const int total = NQ_G + NQ_IH + NQ_HH + NQ_HD;
    for (int i = blockIdx.x * blockDim.x + threadIdx.x; i < total;
         i += gridDim.x * blockDim.x) {
        const float* src; __half* dst; int q;
        if (i < NQ_G)                    { src = Wg;    dst = g_Wg16;              q = i; }
        else if (i < NQ_G + NQ_IH)       { src = Wih;   dst = g_Wih16;             q = i - NQ_G; }
        else if (i < NQ_G + NQ_IH + NQ_HH){ src = Whh;  dst = g_Wih16 + 2304 * G4; q = i - NQ_G - NQ_IH; }
        else                             { src = Whead; dst = g_Whead16;           q = i - NQ_G - NQ_IH - NQ_HH; }
        float4 v = *(const float4*)(src + (size_t)q * 4);
        *(__half2*)(dst + (size_t)q * 4)     = __floats2half2_rn(v.x, v.y);
        *(__half2*)(dst + (size_t)q * 4 + 2) = __floats2half2_rn(v.z, v.w);
    }
}

// ---------------------------------------------------------------------------
// K_cvtf: one-time feat -> fp16 with the order permutation baked in.
// ---------------------------------------------------------------------------
__global__ void __launch_bounds__(256) k_cvtf(const float* __restrict__ feat) {
    int row = blockIdx.x;
    int b = row / PP, p = row % PP;
    const float* src = feat + ((size_t)g_order[b] * PP + p) * EE + threadIdx.x * 8;
    __half* dst = g_feat16 + (size_t)row * EE + threadIdx.x * 8;
    float4 v0 = *(const float4*)(src);
    float4 v1 = *(const float4*)(src + 4);
    *(__half2*)(dst + 0) = __floats2half2_rn(v0.x, v0.y);
    *(__half2*)(dst + 2) = __floats2half2_rn(v0.z, v0.w);
    *(__half2*)(dst + 4) = __floats2half2_rn(v1.x, v1.y);
    *(__half2*)(dst + 6) = __floats2half2_rn(v1.z, v1.w);
}

// ---------------------------------------------------------------------------
// K3: fused launch, grid (98, 5): fe GEMM (fp16 A/out) + mean (y==4)
// ---------------------------------------------------------------------------
__global__ void __launch_bounds__(256) k_fe(const float* __restrict__ feat,
                                            const float* __restrict__ Wf,
                                            const float* __restrict__ bf) {
    int tid = threadIdx.x;
    int mb = blockIdx.x, nb = blockIdx.y;

    if (nb == 4) {
        if (mb >= NB) return;
        int b = mb;
        const float4* base = (const float4*)(feat + (size_t)g_order[b] * PP * EE);
        float4 sA = make_float4(0.f, 0.f, 0.f, 0.f);
        float4 sB = make_float4(0.f, 0.f, 0.f, 0.f);
        #pragma unroll 2
        for (int p = 0; p < PP; ++p) {
            float4 v0 = __ldcs(base + (size_t)p * (EE / 4) + tid);
            float4 v1 = __ldcs(base + (size_t)p * (EE / 4) + tid + 256);
            sA.x += v0.x; sA.y += v0.y; sA.z += v0.z; sA.w += v0.w;
            sB.x += v1.x; sB.y += v1.y; sB.z += v1.z; sB.w += v1.w;
        }
        const float inv = 1.0f / PP;
        sA.x *= inv; sA.y *= inv; sA.z *= inv; sA.w *= inv;
        sB.x *= inv; sB.y *= inv; sB.z *= inv; sB.w *= inv;
        *(float4*)(g_mean + b * EE + tid * 4)        = sA;
        *(float4*)(g_mean + b * EE + 1024 + tid * 4) = sB;
        return;
    }

    __shared__ float As[16][132];
    __shared__ float Bs[16][64];

    float acc[8][4] = {};
    int rb = (tid >> 4) * 8, cb = (tid & 15) * 4;

    int ar = tid >> 1, ak = (tid & 1) * 8;
    int bk = tid >> 4, bn = (tid & 15) * 4;
    const __half* arow = g_feat16 + (size_t)(mb * 128 + ar) * EE;

    for (int k0 = 0; k0 < EE; k0 += 16) {
        {
            uint4 raw = *(const uint4*)(arow + k0 + ak);
            float2 f0 = __half22float2(*reinterpret_cast<__half2*>(&raw.x));
            float2 f1 = __half22float2(*reinterpret_cast<__half2*>(&raw.y));
            float2 f2 = __half22float2(*reinterpret_cast<__half2*>(&raw.z));
            float2 f3 = __half22float2(*reinterpret_cast<__half2*>(&raw.w));
            As[ak + 0][ar] = f0.x; As[ak + 1][ar] = f0.y;
            As[ak + 2][ar] = f1.x; As[ak + 3][ar] = f1.y;
            As[ak + 4][ar] = f2.x; As[ak + 5][ar] = f2.y;
            As[ak + 6][ar] = f3.x; As[ak + 7][ar] = f3.y;
        }
        {
            *(float4*)&Bs[bk][bn] = *(const float4*)(Wf + (size_t)(k0 + bk) * HH + nb * 64 + bn);
        }
        __syncthreads();
        #pragma unroll
        for (int kk = 0; kk < 16; ++kk) {
            float a[8], bv[4];
            *(float4*)(a)     = *(float4*)&As[kk][rb];
            *(float4*)(a + 4) = *(float4*)&As[kk][rb + 4];
            *(float4*)(bv)    = *(float4*)&Bs[kk][cb];
            #pragma unroll
            for (int i = 0; i < 8; ++i)
                #pragma unroll
                for (int j = 0; j < 4; ++j) acc[i][j] += a[i] * bv[j];
        }
        __syncthreads();
    }
    #pragma unroll
    for (int i = 0; i < 8; ++i) {
        int gm = mb * 128 + rb + i;
        int gn = nb * 64 + cb;
        __half2 h01 = __floats2half2_rn(acc[i][0] + bf[gn + 0], acc[i][1] + bf[gn + 1]);
        __half2 h23 = __floats2half2_rn(acc[i][2] + bf[gn + 2], acc[i][3] + bf[gn + 3]);
        *(__half2*)(g_fe16 + (size_t)gm * HH + gn)     = h01;
        *(__half2*)(g_fe16 + (size_t)gm * HH + gn + 2) = h23;
    }
}

// ---------------------------------------------------------------------------
// K2a: init GEMM  mean(64x2048) @ [W_hid | W_cell](2048x512), split-K=8.
// ---------------------------------------------------------------------------
__global__ void __launch_bounds__(256) k_initA(const float* __restrict__ W_hid,
                                               const float* __restrict__ W_cell) {
    __shared__ float As[16][68];
    __shared__ float Bs[16][64];
    int tid = threadIdx.x;
    int nb = blockIdx.x, kc = blockIdx.y;
    const float* wsrc = (nb < 4) ? W_hid : W_cell;
    int ncol0 = (nb & 3) * 64;
    int k0g = kc * 256;
    float acc[4][4] = {};
    int rb = (tid >> 4) * 4, cb = (tid & 15) * 4;

    for (int kt = 0; kt < 256; kt += 16) {
        {
            int r = tid >> 2, kk = (tid & 3) * 4;
            float4 av = *(const float4*)(g_mean + r * EE + k0g + kt + kk);
            As[kk + 0][r] = av.x; As[kk + 1][r] = av.y;
            As[kk + 2][r] = av.z; As[kk + 3][r] = av.w;
        }
        {
            int kk = tid >> 4, n = (tid & 15) * 4;
            *(float4*)&Bs[kk][n] =
                *(const float4*)(wsrc + (size_t)(k0g + kt + kk) * DD + ncol0 + n);
        }
        __syncthreads();
        #pragma unroll
        for (int kk = 0; kk < 16; ++kk) {
            float a[4], bv[4];
            *(float4*)a  = *(float4*)&As[kk][rb];
            *(float4*)bv = *(float4*)&Bs[kk][cb];
            #pragma unroll
            for (int i = 0; i < 4; ++i)
                #pragma unroll
                for (int j = 0; j < 4; ++j) acc[i][j] += a[i] * bv[j];
        }
        __syncthreads();
    }
    #pragma unroll
    for (int i = 0; i < 4; ++i)
        #pragma unroll
        for (int j = 0; j < 4; ++j)
            g_gp[((size_t)kc * NB + rb + i) * 512 + nb * 64 + cb + j] = acc[i][j];
}

__global__ void k_init2(const float* __restrict__ b_hid, const float* __restrict__ b_cell) {
    int b = blockIdx.x, j = threadIdx.x;
    float h = b_hid[j], c = b_cell[j];
    #pragma unroll
    for (int kc = 0; kc < 8; ++kc) {
        const float* p = g_gp + ((size_t)kc * NB + b) * 512;
        h += p[j];
        c += p[256 + j];
    }
    g_h[b * DD + j] = h;
    g_c[b * DD + j] = c;
}

// ===========================================================================
// Persistent step-loop kernel
// ===========================================================================
struct SMu {
    union {
        struct { float As[16][68]; float Bs[16][64]; } g;
        struct { float sh[256]; float she[256]; float swe[256]; } a;
        struct { float sw[256]; float red[8]; } c;
    } u;
};

__device__ __forceinline__ void gridbar() {
    __syncthreads();
    __threadfence();
    if (threadIdx.x == 0) {
        int gen = g_bar_gen;
        if (atomicAdd(&g_bar_count, 1) == NBLK - 1) {
            g_bar_count = 0;
            __threadfence();
            g_bar_gen = gen + 1;
        } else {
            while (g_bar_gen == gen) __nanosleep(64);
        }
    }
    __syncthreads();
    __threadfence();
}

__device__ __forceinline__ void dev_score(int b, int half, SMu& sm,
        const float* __restrict__ Wh, const float* __restrict__ bh,
        const float* __restrict__ We, const float* __restrict__ be) {
    int tid = threadIdx.x, lane = tid & 31, wid = tid >> 5;
    sm.u.a.sh[tid]  = g_h[b * DD + tid];
    sm.u.a.swe[tid] = We[tid];
    __syncthreads();
    float acc = bh[tid];
    #pragma unroll 8
    for (int k = 0; k < DD; ++k) acc += sm.u.a.sh[k] * Wh[k * HH + tid];
    sm.u.a.she[tid] = acc;
    __syncthreads();
    float be0 = be[0];
    int p0 = half * 98, p1 = p0 + 98;
    const __half* febase = g_fe16 + (size_t)b * PP * HH;
    for (int p = p0 + wid; p < p1; p += 8) {
        const __half* fr = febase + (size_t)p * HH;
        float s = 0.f;
        #pragma unroll
        for (int it = 0; it < 4; ++it) {
            int j = it * 64 + lane * 2;
            float2 fv = __half22float2(*(const __half2*)(fr + j));
            float v0 = fv.x + sm.u.a.she[j], v1 = fv.y + sm.u.a.she[j + 1];
            s += fmaxf(v0, 0.f) * sm.u.a.swe[j] + fmaxf(v1, 0.f) * sm.u.a.swe[j + 1];
        }
        #pragma unroll
        for (int o = 16; o; o >>= 1) s += __shfl_xor_sync(0xffffffffu, s, o);
        if (lane == 0) g_score[b * PP + p] = s + be0;
    }
}

__device__ __forceinline__ void dev_gpre(int bid, SMu& sm) {
    int tid = threadIdx.x;
    int nb = bid & 31, kc = bid >> 5;
    int kbase = kc * 128;
    float acc[4][4] = {};
    int rb = (tid >> 4) * 4, cb = (tid & 15) * 4;

    for (int kt = 0; kt < 128; kt += 16) {
        {
            int r = tid >> 2, kk = (tid & 3) * 4;
            float4 av = *(const float4*)(g_h + r * DD + kbase + kt + kk);
            sm.u.g.As[kk + 0][r] = av.x; sm.u.g.As[kk + 1][r] = av.y;
            sm.u.g.As[kk + 2][r] = av.z; sm.u.g.As[kk + 3][r] = av.w;
        }
        {
            int kk = tid >> 4, n = (tid & 15) * 4;
            const __half* src = g_Wg16 + (size_t)(kbase + kt + kk) * EE + nb * 64 + n;
            float2 f0 = __half22float2(*(const __half2*)(src));
            float2 f1 = __half22float2(*(const __half2*)(src + 2));
            sm.u.g.Bs[kk][n + 0] = f0.x; sm.u.g.Bs[kk][n + 1] = f0.y;
            sm.u.g.Bs[kk][n + 2] = f1.x; sm.u.g.Bs[kk][n + 3] = f1.y;
        }
        __syncthreads();
        #pragma unroll
        for (int kk = 0; kk < 16; ++kk) {
            float a[4], bv[4];
            *(float4*)a  = *(float4*)&sm.u.g.As[kk][rb];
            *(float4*)bv = *(float4*)&sm.u.g.Bs[kk][cb];
            #pragma unroll
            for (int i = 0; i < 4; ++i)
                #pragma unroll
                for (int j = 0; j < 4; ++j) acc[i][j] += a[i] * bv[j];
        }
        __syncthreads();
    }
    #pragma unroll
    for (int i = 0; i < 4; ++i)
        #pragma unroll
        for (int j = 0; j < 4; ++j)
            g_gatep[((size_t)kc * NB + rb + i) * EE + nb * 64 + cb + j] = acc[i][j];
}

__device__ __forceinline__ void dev_head(int nb, int tprev, SMu& sm,
        const float* __restrict__ b_head, float* __restrict__ out) {
    int tid = threadIdx.x;
    int n0 = nb * 64;
    float acc[4][4] = {};
    int rb = (tid >> 4) * 4, cb = (tid & 15) * 4;

    for (int k0 = 0; k0 < DD; k0 += 16) {
        {
            int r = tid >> 2, kk = (tid & 3) * 4;
            float4 av = *(const float4*)(g_h + r * DD + k0 + kk);
            sm.u.g.As[kk + 0][r] = av.x; sm.u.g.As[kk + 1][r] = av.y;
            sm.u.g.As[kk + 2][r] = av.z; sm.u.g.As[kk + 3][r] = av.w;
        }
        {
            int kk = tid >> 4, n = (tid & 15) * 4;
            int gn = n0 + n;
            const __half* src = g_Whead16 + (size_t)(k0 + kk) * VV + gn;
            float b0, b1, b2, b3;
            if (gn + 3 < VV) {
                float2 f0 = __half22float2(*(const __half2*)(src));
                float2 f1 = __half22float2(*(const __half2*)(src + 2));
                b0 = f0.x; b1 = f0.y; b2 = f1.x; b3 = f1.y;
            } else {
                b0 = (gn + 0 < VV) ? __half2float(src[0]) : 0.f;
                b1 = (gn + 1 < VV) ? __half2float(src[1]) : 0.f;
                b2 = (gn + 2 < VV) ? __half2float(src[2]) : 0.f;
                b3 = (gn + 3 < VV) ? __half2float(src[3]) : 0.f;
            }
            sm.u.g.Bs[kk][n + 0] = b0; sm.u.g.Bs[kk][n + 1] = b1;
            sm.u.g.Bs[kk][n + 2] = b2; sm.u.g.Bs[kk][n + 3] = b3;
        }
        __syncthreads();
        #pragma unroll
        for (int kk = 0; kk < 16; ++kk) {
            float a[4], bv[4];
            *(float4*)a  = *(float4*)&sm.u.g.As[kk][rb];
            *(float4*)bv = *(float4*)&sm.u.g.Bs[kk][cb];
            #pragma unroll
            for (int i = 0; i < 4; ++i)
                #pragma unroll
                for (int j = 0; j < 4; ++j) acc[i][j] += a[i] * bv[j];
        }
        __syncthreads();
    }
    #pragma unroll
    for (int i = 0; i < 4; ++i) {
        int b = rb + i;
        bool msk = (g_target[b] > tprev);
        size_t rowbase = ((size_t)b * TT + tprev) * VV;
        #pragma unroll
        for (int j = 0; j < 4; ++j) {
            int gn = n0 + cb + j;
            if (gn < VV) out[rowbase + gn] = msk ? (acc[i][j] + b_head[gn]) : 0.f;
        }
    }
}

__device__ __forceinline__ void dev_ctx(int b, int half, int t, SMu& sm,
        const float* __restrict__ b_gate, const float* __restrict__ emb,
        const int* __restrict__ tok, float* __restrict__ out_att) {
    int tid = threadIdx.x, lane = tid & 31, wid = tid >> 5;

    // softmax over 196 scores (all 8 warps)
    float v = (tid < PP) ? g_score[b * PP + tid] : -3.4e38f;
    float m = v;
    #pragma unroll
    for (int o = 16; o; o >>= 1) m = fmaxf(m, __shfl_xor_sync(0xffffffffu, m, o));
    if (lane == 0) sm.u.c.red[wid] = m;
    __syncthreads();
    if (tid == 0) {
        float mm = sm.u.c.red[0];
        #pragma unroll
        for (int i = 1; i < 8; ++i) mm = fmaxf(mm, sm.u.c.red[i]);
        sm.u.c.red[0] = mm;
    }
    __syncthreads();
    float mx = sm.u.c.red[0];
    __syncthreads();

    float e = (tid < PP) ? expf(v - mx) : 0.f;
    float s = e;
    #pragma unroll
    for (int o = 16; o; o >>= 1) s += __shfl_xor_sync(0xffffffffu, s, o);
    if (lane == 0) sm.u.c.red[wid] = s;
    __syncthreads();
    if (tid == 0) {
        float ss = 0.f;
        #pragma unroll
        for (int i = 0; i < 8; ++i) ss += sm.u.c.red[i];
        sm.u.c.red[0] = ss;
    }
    __syncthreads();
    float inv = 1.0f / sm.u.c.red[0];
    if (tid < PP) sm.u.c.sw[tid] = e * inv;
    __syncthreads();

    if (half == 0) {
        bool msk = (g_target[b] > t);
        if (tid < PP)
            out_att[((size_t)b * TT + t) * PP + tid] = msk ? sm.u.c.sw[tid] : 0.f;
        int token = tok[g_order[b] * LL + t];
        g_x[b * XK + tid] = emb[(size_t)token * EMB + tid];
        g_x[b * XK + EMB + EE + tid] = g_h[b * DD + tid];
    }

    // ctx scan over fp16 feat
    int e0i = half * 1024 + tid * 4;
    const __half* fb = g_feat16 + (size_t)b * PP * EE + e0i;

    float4 s0 = make_float4(0.f, 0.f, 0.f, 0.f);
    float4 s1 = make_float4(0.f, 0.f, 0.f, 0.f);
    float4 s2 = make_float4(0.f, 0.f, 0.f, 0.f);
    float4 s3 = make_float4(0.f, 0.f, 0.f, 0.f);
    for (int p = 0; p < PP; p += 4) {
        float w0 = sm.u.c.sw[p], w1 = sm.u.c.sw[p + 1];
        float w2 = sm.u.c.sw[p + 2], w3 = sm.u.c.sw[p + 3];
        uint2 r0 = __ldcs((const uint2*)(fb + (size_t)(p + 0) * EE));
        uint2 r1 = __ldcs((const uint2*)(fb + (size_t)(p + 1) * EE));
        uint2 r2 = __ldcs((const uint2*)(fb + (size_t)(p + 2) * EE));
        uint2 r3 = __ldcs((const uint2*)(fb + (size_t)(p + 3) * EE));
        float2 a0 = __half22float2(*reinterpret_cast<__half2*>(&r0.x));
        float2 c0 = __half22float2(*reinterpret_cast<__half2*>(&r0.y));
        float2 a1 = __half22float2(*reinterpret_cast<__half2*>(&r1.x));
        float2 c1 = __half22float2(*reinterpret_cast<__half2*>(&r1.y));
        float2 a2 = __half22float2(*reinterpret_cast<__half2*>(&r2.x));
        float2 c2 = __half22float2(*reinterpret_cast<__half2*>(&r2.y));
        float2 a3 = __half22float2(*reinterpret_cast<__half2*>(&r3.x));
        float2 c3 = __half22float2(*reinterpret_cast<__half2*>(&r3.y));
        s0.x += w0 * a0.x; s0.y += w0 * a0.y; s0.z += w0 * c0.x; s0.w += w0 * c0.y;
        s1.x += w1 * a1.x; s1.y += w1 * a1.y; s1.z += w1 * c1.x; s1.w += w1 * c1.y;
        s2.x += w2 * a2.x; s2.y += w2 * a2.y; s2.z += w2 * c2.x; s2.w += w2 * c2.y;
        s3.x += w3 * a3.x; s3.y += w3 * a3.y; s3.z += w3 * c3.x; s3.w += w3 * c3.y;
    }
    float4 sum;
    sum.x = (s0.x + s1.x) + (s2.x + s3.x);
    sum.y = (s0.y + s1.y) + (s2.y + s3.y);
    sum.z = (s0.z + s1.z) + (s2.z + s3.z);
    sum.w = (s0.w + s1.w) + (s2.w + s3.w);

    float4 gp0 = *(const float4*)(g_gatep + (size_t)b * EE + e0i);
    float4 gp1 = *(const float4*)(g_gatep + ((size_t)NB + b) * EE + e0i);
    float4 bg  = *(const float4*)(b_gate + e0i);
    float4 ctx;
    ctx.x = sum.x * sigf(bg.x + gp0.x + gp1.x);
    ctx.y = sum.y * sigf(bg.y + gp0.y + gp1.y);
    ctx.z = sum.z * sigf(bg.z + gp0.z + gp1.z);
    ctx.w = sum.w * sigf(bg.w + gp0.w + gp1.w);
    *(float4*)(g_x + (size_t)b * XK + EMB + e0i) = ctx;
}

__device__ __forceinline__ void dev_gates(int nb, int kc, SMu& sm) {
    int tid = threadIdx.x;
    int k0g = kc * 256;
    const __half* wbase = g_Wih16 + (size_t)k0g * G4;
    float acc[4][4] = {};
    int rb = (tid >> 4) * 4, cb = (tid & 15) * 4;

    for (int kt = 0; kt < 256; kt += 16) {
        {
            int r = tid >> 2, kk = (tid & 3) * 4;
            float4 av = *(const float4*)(g_x + r * XK + k0g + kt + kk);
            sm.u.g.As[kk + 0][r] = av.x; sm.u.g.As[kk + 1][r] = av.y;
            sm.u.g.As[kk + 2][r] = av.z; sm.u.g.As[kk + 3][r] = av.w;
        }
        {
            int kk = tid >> 4, n = (tid & 15) * 4;
            const __half* src = wbase + (size_t)(kt + kk) * G4 + nb * 64 + n;
            float2 f0 = __half22float2(*(const __half2*)(src));
            float2 f1 = __half22float2(*(const __half2*)(src + 2));
            sm.u.g.Bs[kk][n + 0] = f0.x; sm.u.g.Bs[kk][n + 1] = f0.y;
            sm.u.g.Bs[kk][n + 2] = f1.x; sm.u.g.Bs[kk][n + 3] = f1.y;
        }
        __syncthreads();
        #pragma unroll
        for (int kk = 0; kk < 16; ++kk) {
            float a[4], bv[4];
            *(float4*)a  = *(float4*)&sm.u.g.As[kk][rb];
            *(float4*)bv = *(float4*)&sm.u.g.Bs[kk][cb];
            #pragma unroll
            for (int i = 0; i < 4; ++i)
                #pragma unroll
                for (int j = 0; j < 4; ++j) acc[i][j] += a[i] * bv[j];
        }
        __syncthreads();
    }
    #pragma unroll
    for (int i = 0; i < 4; ++i)
        #pragma unroll
        for (int j = 0; j < 4; ++j)
            g_gp[((size_t)kc * NB + rb + i) * G4 + nb * 64 + cb + j] = acc[i][j];
}

__device__ __forceinline__ void dev_lstm(int b, int t,
        const float* __restrict__ b_ih, const float* __restrict__ b_hh) {
    int j = threadIdx.x;
    float gi = b_ih[j] + b_hh[j];
    float gf = b_ih[DD + j] + b_hh[DD + j];
    float gg = b_ih[2 * DD + j] + b_hh[2 * DD + j];
    float go = b_ih[3 * DD + j] + b_hh[3 * DD + j];
    #pragma unroll
    for (int kc = 0; kc < KC; ++kc) {
        const float* p = g_gp + ((size_t)kc * NB + b) * G4;
        gi += p[j];
        gf += p[DD + j];
        gg += p[2 * DD + j];
        go += p[3 * DD + j];
    }
    float c = g_c[b * DD + j];
    float cn = sigf(gf) * c + sigf(gi) * tanhf(gg);
    float hn = sigf(go) * tanhf(cn);
    if (g_target[b] > t) {
        g_h[b * DD + j] = hn;
        g_c[b * DD + j] = cn;
    }
}

__global__ void __launch_bounds__(256, 2) k_loop(
        const float* __restrict__ Wh, const float* __restrict__ bh,
        const float* __restrict__ We, const float* __restrict__ be,
        const float* __restrict__ b_gate, const float* __restrict__ emb,
        const int* __restrict__ tok,
        const float* __restrict__ b_ih, const float* __restrict__ b_hh,
        const float* __restrict__ b_head,
        float* __restrict__ out, float* __restrict__ out_att) {
    __shared__ SMu sm;
    for (int t = 0; t <= TT; ++t) {
        // Phase A: scores(t) + gpre(t) (if t<TT) and head(t-1) (if t>=1)
        int nA = (t < TT ? 192 : 0) + (t >= 1 ? 157 : 0);
        int headbase = (t < TT) ? 192 : 0;
        for (int u = blockIdx.x; u < nA; u += NBLK) {
            __syncthreads();
            if (t < TT && u < 128)      dev_score(u >> 1, u & 1, sm, Wh, bh, We, be);
            else if (t < TT && u < 192) dev_gpre(u - 128, sm);
            else                        dev_head(u - headbase, t - 1, sm, b_head, out);
        }
        if (t == TT) break;
        gridbar();
        // Phase B: softmax + ctx + x assembly (128 units)
        for (int u = blockIdx.x; u < 128; u += NBLK) {
            __syncthreads();
            dev_ctx(u >> 1, u & 1, t, sm, b_gate, emb, tok, out_att);
        }
        gridbar();
        // Phase C: gates split-K GEMM (160 units)
        for (int u = blockIdx.x; u < 160; u += NBLK) {
            __syncthreads();
            dev_gates(u & 15, u >> 4, sm);
        }
        gridbar();
        // Phase D: LSTM pointwise (64 units)
        if (blockIdx.x < NB) dev_lstm(blockIdx.x, t, b_ih, b_hh);
        gridbar();
    }
}

// ---------------------------------------------------------------------------
extern "C" void kernel_launch(void* const* d_in, const int* in_sizes, int n_in,
                              void* d_out, int out_size) {
    const float* feat   = (const float*)d_in[0];
    const int*   tok    = (const int*)d_in[1];
    const int*   caplen = (const int*)d_in[2];
    const float* Wf     = (const float*)d_in[3];
    const float* bf     = (const float*)d_in[4];
    const float* Wh     = (const float*)d_in[5];
    const float* bh     = (const float*)d_in[6];
    const float* We     = (const float*)d_in[7];
    const float* be     = (const float*)d_in[8];
    const float* emb    = (const float*)d_in[9];
    const float* W_ih   = (const float*)d_in[10];
    const float* b_ih   = (const float*)d_in[11];
    const float* W_hh   = (const float*)d_in[12];
    const float* b_hh   = (const float*)d_in[13];
    const float* W_hid  = (const float*)d_in[14];
    const float* b_hid  = (const float*)d_in[15];
    const float* W_cell = (const float*)d_in[16];
    const float* b_cell = (const float*)d_in[17];
    const float* W_gate = (const float*)d_in[18];
    const float* b_gate = (const float*)d_in[19];
    const float* W_head = (const float*)d_in[20];
    const float* b_head = (const float*)d_in[21];

    float* out = (float*)d_out;
    float* out_att = out + (size_t)NB * TT * VV;

    k_order<<<1, 32>>>(caplen);
    k_cvt<<<512, 256>>>(W_gate, W_ih, W_hh, W_head);
    k_cvtf<<<NB * PP, 256>>>(feat);
    k_fe<<<dim3(98, 5), 256>>>(feat, Wf, bf);     // fe GEMM (fp16 A/out) + mean
    k_initA<<<dim3(8, 8), 256>>>(W_hid, W_cell);  // init GEMM, split-K
    k_init2<<<NB, 256>>>(b_hid, b_cell);

    // entire 31-step decoder loop in ONE persistent kernel
    k_loop<<<NBLK, 256>>>(Wh, bh, We, be, b_gate, emb, tok,
                          b_ih, b_hh, b_head, out, out_att);
}

// round 8
// speedup vs baseline: 1.3490x; 1.1543x over previous
#include <cuda_runtime.h>
#include <cuda_fp16.h>

static constexpr int NB  = 64;     // batch
static constexpr int PP  = 196;    // spatial positions
static constexpr int EE  = 2048;   // feature dim
static constexpr int DD  = 256;    // hidden
static constexpr int HH  = 256;    // attention hidden
static constexpr int EMB = 256;    // embedding
static constexpr int VV  = 10000;  // vocab
static constexpr int LL  = 32;     // caption length
static constexpr int TT  = 31;     // timesteps
static constexpr int XK  = EMB + EE + DD;  // 2560
static constexpr int G4  = 4 * DD;         // 1024
static constexpr int KC  = 10;             // split-K chunks for gates gemm
static constexpr int NBLK = 256;           // persistent grid size

__device__ int    g_order[NB];
__device__ int    g_target[NB];
__device__ __half g_feat16[NB * PP * EE];   // 51.4 MB fp16 feat, order-permuted
__device__ __half g_fe16[NB * PP * HH];     // 6.4 MB fp16 attention features
__device__ float  g_mean[NB * EE];
__device__ float  g_h[NB * DD];
__device__ float  g_c[NB * DD];
__device__ float  g_score[NB * PP];
__device__ float  g_x[NB * XK];
__device__ float  g_gp[KC * NB * G4];       // split-K partials (gates / init)
__device__ float  g_gatep[2 * NB * EE];     // split-K partials for gate pre-act
__device__ __half g_Wg16[DD * EE];          // W_gate fp16
__device__ __half g_Wih16[XK * G4];         // [W_ih ; W_hh] fp16 concat
__device__ __half g_Whead16[DD * VV];       // W_head fp16

// software grid barrier state (count always returns to 0; gen monotonic)
__device__ int          g_bar_count;
__device__ volatile int g_bar_gen;

__device__ __forceinline__ float sigf(float x) { return 1.0f / (1.0f + expf(-x)); }

// ---------------------------------------------------------------------------
// K0: stable descending counting sort of lengths (matches jnp.argsort(-len))
// ---------------------------------------------------------------------------
__global__ void k_order(const int* __restrict__ caplen) {
    if (threadIdx.x == 0) {
        int idx = 0;
        for (int v = LL; v >= 1; --v) {
            for (int i = 0; i < NB; ++i) {
                if (caplen[i] == v) {
                    g_order[idx]  = i;
                    g_target[idx] = v - 1;
                    ++idx;
                }
            }
        }
    }
}

// ---------------------------------------------------------------------------
// K_cvt: one-time fp32 -> fp16 conversion of step-loop weights
// ---------------------------------------------------------------------------
__global__ void k_cvt(const float* __restrict__ Wg, const float* __restrict__ Wih,
                      const float* __restrict__ Whh, const float* __restrict__ Whead) {
    const int NQ_G  = (DD * EE) / 4;
    const int NQ_IH = (2304 * G4) / 4;
    const int NQ_HH = (DD * G4) / 4;
    const int NQ_HD = (DD * VV) / 4;
    const int total = NQ_G + NQ_IH + NQ_HH + NQ_HD;
    for (int i = blockIdx.x * blockDim.x + threadIdx.x; i < total;
         i += gridDim.x * blockDim.x) {
        const float* src; __half* dst; int q;
        if (i < NQ_G)                    { src = Wg;    dst = g_Wg16;              q = i; }
        else if (i < NQ_G + NQ_IH)       { src = Wih;   dst = g_Wih16;             q = i - NQ_G; }
        else if (i < NQ_G + NQ_IH + NQ_HH){ src = Whh;  dst = g_Wih16 + 2304 * G4; q = i - NQ_G - NQ_IH; }
        else                             { src = Whead; dst = g_Whead16;           q = i - NQ_G - NQ_IH - NQ_HH; }
        float4 v = *(const float4*)(src + (size_t)q * 4);
        *(__half2*)(dst + (size_t)q * 4)     = __floats2half2_rn(v.x, v.y);
        *(__half2*)(dst + (size_t)q * 4 + 2) = __floats2half2_rn(v.z, v.w);
    }
}

// ---------------------------------------------------------------------------
// K_cvtf: one-time feat -> fp16 with the order permutation baked in.
// ---------------------------------------------------------------------------
__global__ void __launch_bounds__(256) k_cvtf(const float* __restrict__ feat) {
    int row = blockIdx.x;
    int b = row / PP, p = row % PP;
    const float* src = feat + ((size_t)g_order[b] * PP + p) * EE + threadIdx.x * 8;
    __half* dst = g_feat16 + (size_t)row * EE + threadIdx.x * 8;
    float4 v0 = *(const float4*)(src);
    float4 v1 = *(const float4*)(src + 4);
    *(__half2*)(dst + 0) = __floats2half2_rn(v0.x, v0.y);
    *(__half2*)(dst + 2) = __floats2half2_rn(v0.z, v0.w);
    *(__half2*)(dst + 4) = __floats2half2_rn(v1.x, v1.y);
    *(__half2*)(dst + 6) = __floats2half2_rn(v1.z, v1.w);
}

// ---------------------------------------------------------------------------
// K3: fused launch, grid (98, 5): fe GEMM (fp16 A/out, f32x2 FMA) + mean (y==4)
// ---------------------------------------------------------------------------
__global__ void __launch_bounds__(256) k_fe(const float* __restrict__ feat,
                                            const float* __restrict__ Wf,
                                            const float* __restrict__ bf) {
    int tid = threadIdx.x;
    int mb = blockIdx.x, nb = blockIdx.y;

    if (nb == 4) {
        if (mb >= NB) return;
        int b = mb;
        const float4* base = (const float4*)(feat + (size_t)g_order[b] * PP * EE);
        float4 sA = make_float4(0.f, 0.f, 0.f, 0.f);
        float4 sB = make_float4(0.f, 0.f, 0.f, 0.f);
        #pragma unroll 2
        for (int p = 0; p < PP; ++p) {
            float4 v0 = __ldcs(base + (size_t)p * (EE / 4) + tid);
            float4 v1 = __ldcs(base + (size_t)p * (EE / 4) + tid + 256);
            sA.x += v0.x; sA.y += v0.y; sA.z += v0.z; sA.w += v0.w;
            sB.x += v1.x; sB.y += v1.y; sB.z += v1.z; sB.w += v1.w;
        }
        const float inv = 1.0f / PP;
        sA.x *= inv; sA.y *= inv; sA.z *= inv; sA.w *= inv;
        sB.x *= inv; sB.y *= inv; sB.z *= inv; sB.w *= inv;
        *(float4*)(g_mean + b * EE + tid * 4)        = sA;
        *(float4*)(g_mean + b * EE + 1024 + tid * 4) = sB;
        return;
    }

    __shared__ float As[16][132];
    __shared__ float Bs[16][64];

    // packed f32x2 accumulators: acc2[k2][j] = {row 2k2, row 2k2+1} of col j
    unsigned long long acc2[4][4];
    #pragma unroll
    for (int k2 = 0; k2 < 4; ++k2)
        #pragma unroll
        for (int j = 0; j < 4; ++j) acc2[k2][j] = 0ull;

    int rb = (tid >> 4) * 8, cb = (tid & 15) * 4;
    int ar = tid >> 1, ak = (tid & 1) * 8;
    int bk = tid >> 4, bn = (tid & 15) * 4;
    const __half* arow = g_feat16 + (size_t)(mb * 128 + ar) * EE;

    for (int k0 = 0; k0 < EE; k0 += 16) {
        {
            uint4 raw = *(const uint4*)(arow + k0 + ak);
            float2 f0 = __half22float2(*reinterpret_cast<__half2*>(&raw.x));
            float2 f1 = __half22float2(*reinterpret_cast<__half2*>(&raw.y));
            float2 f2 = __half22float2(*reinterpret_cast<__half2*>(&raw.z));
            float2 f3 = __half22float2(*reinterpret_cast<__half2*>(&raw.w));
            As[ak + 0][ar] = f0.x; As[ak + 1][ar] = f0.y;
            As[ak + 2][ar] = f1.x; As[ak + 3][ar] = f1.y;
            As[ak + 4][ar] = f2.x; As[ak + 5][ar] = f2.y;
            As[ak + 6][ar] = f3.x; As[ak + 7][ar] = f3.y;
        }
        {
            *(float4*)&Bs[bk][bn] = *(const float4*)(Wf + (size_t)(k0 + bk) * HH + nb * 64 + bn);
        }
        __syncthreads();
        #pragma unroll
        for (int kk = 0; kk < 16; ++kk) {
            float a[8], bv[4];
            *(float4*)(a)     = *(float4*)&As[kk][rb];
            *(float4*)(a + 4) = *(float4*)&As[kk][rb + 4];
            *(float4*)(bv)    = *(float4*)&Bs[kk][cb];
            unsigned long long aa[4], bb[4];
            #pragma unroll
            for (int k2 = 0; k2 < 4; ++k2)
                asm("mov.b64 %0, {%1, %2};" : "=l"(aa[k2]) : "f"(a[2 * k2]), "f"(a[2 * k2 + 1]));
            #pragma unroll
            for (int j = 0; j < 4; ++j)
                asm("mov.b64 %0, {%1, %2};" : "=l"(bb[j]) : "f"(bv[j]), "f"(bv[j]));
            #pragma unroll
            for (int k2 = 0; k2 < 4; ++k2)
                #pragma unroll
                for (int j = 0; j < 4; ++j)
                    asm("fma.rn.f32x2 %0, %1, %2, %0;"
                        : "+l"(acc2[k2][j]) : "l"(aa[k2]), "l"(bb[j]));
        }
        __syncthreads();
    }
    #pragma unroll
    for (int k2 = 0; k2 < 4; ++k2) {
        float lo[4], hi[4];
        #pragma unroll
        for (int j = 0; j < 4; ++j)
            asm("mov.b64 {%0, %1}, %2;" : "=f"(lo[j]), "=f"(hi[j]) : "l"(acc2[k2][j]));
        int gn = nb * 64 + cb;
        {
            int gm = mb * 128 + rb + 2 * k2;
            __half2 h01 = __floats2half2_rn(lo[0] + bf[gn + 0], lo[1] + bf[gn + 1]);
            __half2 h23 = __floats2half2_rn(lo[2] + bf[gn + 2], lo[3] + bf[gn + 3]);
            *(__half2*)(g_fe16 + (size_t)gm * HH + gn)     = h01;
            *(__half2*)(g_fe16 + (size_t)gm * HH + gn + 2) = h23;
        }
        {
            int gm = mb * 128 + rb + 2 * k2 + 1;
            __half2 h01 = __floats2half2_rn(hi[0] + bf[gn + 0], hi[1] + bf[gn + 1]);
            __half2 h23 = __floats2half2_rn(hi[2] + bf[gn + 2], hi[3] + bf[gn + 3]);
            *(__half2*)(g_fe16 + (size_t)gm * HH + gn)     = h01;
            *(__half2*)(g_fe16 + (size_t)gm * HH + gn + 2) = h23;
        }
    }
}

// ---------------------------------------------------------------------------
// K2a: init GEMM  mean(64x2048) @ [W_hid | W_cell](2048x512), split-K=8.
// ---------------------------------------------------------------------------
__global__ void __launch_bounds__(256) k_initA(const float* __restrict__ W_hid,
                                               const float* __restrict__ W_cell) {
    __shared__ float As[16][68];
    __shared__ float Bs[16][64];
    int tid = threadIdx.x;
    int nb = blockIdx.x, kc = blockIdx.y;
    const float* wsrc = (nb < 4) ? W_hid : W_cell;
    int ncol0 = (nb & 3) * 64;
    int k0g = kc * 256;
    float acc[4][4] = {};
    int rb = (tid >> 4) * 4, cb = (tid & 15) * 4;

    for (int kt = 0; kt < 256; kt += 16) {
        {
            int r = tid >> 2, kk = (tid & 3) * 4;
            float4 av = *(const float4*)(g_mean + r * EE + k0g + kt + kk);
            As[kk + 0][r] = av.x; As[kk + 1][r] = av.y;
            As[kk + 2][r] = av.z; As[kk + 3][r] = av.w;
        }
        {
            int kk = tid >> 4, n = (tid & 15) * 4;
            *(float4*)&Bs[kk][n] =
                *(const float4*)(wsrc + (size_t)(k0g + kt + kk) * DD + ncol0 + n);
        }
        __syncthreads();
        #pragma unroll
        for (int kk = 0; kk < 16; ++kk) {
            float a[4], bv[4];
            *(float4*)a  = *(float4*)&As[kk][rb];
            *(float4*)bv = *(float4*)&Bs[kk][cb];
            #pragma unroll
            for (int i = 0; i < 4; ++i)
                #pragma unroll
                for (int j = 0; j < 4; ++j) acc[i][j] += a[i] * bv[j];
        }
        __syncthreads();
    }
    #pragma unroll
    for (int i = 0; i < 4; ++i)
        #pragma unroll
        for (int j = 0; j < 4; ++j)
            g_gp[((size_t)kc * NB + rb + i) * 512 + nb * 64 + cb + j] = acc[i][j];
}

__global__ void k_init2(const float* __restrict__ b_hid, const float* __restrict__ b_cell) {
    int b = blockIdx.x, j = threadIdx.x;
    float h = b_hid[j], c = b_cell[j];
    #pragma unroll
    for (int kc = 0; kc < 8; ++kc) {
        const float* p = g_gp + ((size_t)kc * NB + b) * 512;
        h += p[j];
        c += p[256 + j];
    }
    g_h[b * DD + j] = h;
    g_c[b * DD + j] = c;
}

// ===========================================================================
// Persistent step-loop kernel
// ===========================================================================
struct SMu {
    union {
        struct { float As[16][68]; float Bs[16][64]; } g;
        struct { float sh[256]; float she[256]; float swe[256]; } a;
        struct { float sw[256]; float red[8]; } c;
    } u;
};

__device__ __forceinline__ void gridbar() {
    __syncthreads();
    __threadfence();
    if (threadIdx.x == 0) {
        int gen = g_bar_gen;
        if (atomicAdd(&g_bar_count, 1) == NBLK - 1) {
            g_bar_count = 0;
            __threadfence();
            g_bar_gen = gen + 1;
        } else {
            while (g_bar_gen == gen) __nanosleep(64);
        }
    }
    __syncthreads();
    __threadfence();
}

__device__ __forceinline__ void dev_score(int b, int half, SMu& sm,
        const float* __restrict__ Wh, const float* __restrict__ bh,
        const float* __restrict__ We, const float* __restrict__ be) {
    int tid = threadIdx.x, lane = tid & 31, wid = tid >> 5;
    sm.u.a.sh[tid]  = g_h[b * DD + tid];
    sm.u.a.swe[tid] = We[tid];
    __syncthreads();
    float acc = bh[tid];
    #pragma unroll 8
    for (int k = 0; k < DD; ++k) acc += sm.u.a.sh[k] * Wh[k * HH + tid];
    sm.u.a.she[tid] = acc;
    __syncthreads();
    float be0 = be[0];
    int p0 = half * 98, p1 = p0 + 98;
    const __half* febase = g_fe16 + (size_t)b * PP * HH;
    for (int p = p0 + wid; p < p1; p += 8) {
        const __half* fr = febase + (size_t)p * HH;
        float s = 0.f;
        #pragma unroll
        for (int it = 0; it < 4; ++it) {
            int j = it * 64 + lane * 2;
            float2 fv = __half22float2(*(const __half2*)(fr + j));
            float v0 = fv.x + sm.u.a.she[j], v1 = fv.y + sm.u.a.she[j + 1];
            s += fmaxf(v0, 0.f) * sm.u.a.swe[j] + fmaxf(v1, 0.f) * sm.u.a.swe[j + 1];
        }
        #pragma unroll
        for (int o = 16; o; o >>= 1) s += __shfl_xor_sync(0xffffffffu, s, o);
        if (lane == 0) g_score[b * PP + p] = s + be0;
    }
}

__device__ __forceinline__ void dev_gpre(int bid, SMu& sm) {
    int tid = threadIdx.x;
    int nb = bid & 31, kc = bid >> 5;
    int kbase = kc * 128;
    float acc[4][4] = {};
    int rb = (tid >> 4) * 4, cb = (tid & 15) * 4;

    for (int kt = 0; kt < 128; kt += 16) {
        {
            int r = tid >> 2, kk = (tid & 3) * 4;
            float4 av = *(const float4*)(g_h + r * DD + kbase + kt + kk);
            sm.u.g.As[kk + 0][r] = av.x; sm.u.g.As[kk + 1][r] = av.y;
            sm.u.g.As[kk + 2][r] = av.z; sm.u.g.As[kk + 3][r] = av.w;
        }
        {
            int kk = tid >> 4, n = (tid & 15) * 4;
            const __half* src = g_Wg16 + (size_t)(kbase + kt + kk) * EE + nb * 64 + n;
            float2 f0 = __half22float2(*(const __half2*)(src));
            float2 f1 = __half22float2(*(const __half2*)(src + 2));
            sm.u.g.Bs[kk][n + 0] = f0.x; sm.u.g.Bs[kk][n + 1] = f0.y;
            sm.u.g.Bs[kk][n + 2] = f1.x; sm.u.g.Bs[kk][n + 3] = f1.y;
        }
        __syncthreads();
        #pragma unroll
        for (int kk = 0; kk < 16; ++kk) {
            float a[4], bv[4];
            *(float4*)a  = *(float4*)&sm.u.g.As[kk][rb];
            *(float4*)bv = *(float4*)&sm.u.g.Bs[kk][cb];
            #pragma unroll
            for (int i = 0; i < 4; ++i)
                #pragma unroll
                for (int j = 0; j < 4; ++j) acc[i][j] += a[i] * bv[j];
        }
        __syncthreads();
    }
    #pragma unroll
    for (int i = 0; i < 4; ++i)
        #pragma unroll
        for (int j = 0; j < 4; ++j)
            g_gatep[((size_t)kc * NB + rb + i) * EE + nb * 64 + cb + j] = acc[i][j];
}

__device__ __forceinline__ void dev_head(int nb, int tprev, SMu& sm,
        const float* __restrict__ b_head, float* __restrict__ out) {
    int tid = threadIdx.x;
    int n0 = nb * 64;
    float acc[4][4] = {};
    int rb = (tid >> 4) * 4, cb = (tid & 15) * 4;

    for (int k0 = 0; k0 < DD; k0 += 16) {
        {
            int r = tid >> 2, kk = (tid & 3) * 4;
            float4 av = *(const float4*)(g_h + r * DD + k0 + kk);
            sm.u.g.As[kk + 0][r] = av.x; sm.u.g.As[kk + 1][r] = av.y;
            sm.u.g.As[kk + 2][r] = av.z; sm.u.g.As[kk + 3][r] = av.w;
        }
        {
            int kk = tid >> 4, n = (tid & 15) * 4;
            int gn = n0 + n;
            const __half* src = g_Whead16 + (size_t)(k0 + kk) * VV + gn;
            float b0, b1, b2, b3;
            if (gn + 3 < VV) {
                float2 f0 = __half22float2(*(const __half2*)(src));
                float2 f1 = __half22float2(*(const __half2*)(src + 2));
                b0 = f0.x; b1 = f0.y; b2 = f1.x; b3 = f1.y;
            } else {
                b0 = (gn + 0 < VV) ? __half2float(src[0]) : 0.f;
                b1 = (gn + 1 < VV) ? __half2float(src[1]) : 0.f;
                b2 = (gn + 2 < VV) ? __half2float(src[2]) : 0.f;
                b3 = (gn + 3 < VV) ? __half2float(src[3]) : 0.f;
            }
            sm.u.g.Bs[kk][n + 0] = b0; sm.u.g.Bs[kk][n + 1] = b1;
            sm.u.g.Bs[kk][n + 2] = b2; sm.u.g.Bs[kk][n + 3] = b3;
        }
        __syncthreads();
        #pragma unroll
        for (int kk = 0; kk < 16; ++kk) {
            float a[4], bv[4];
            *(float4*)a  = *(float4*)&sm.u.g.As[kk][rb];
            *(float4*)bv = *(float4*)&sm.u.g.Bs[kk][cb];
            #pragma unroll
            for (int i = 0; i < 4; ++i)
                #pragma unroll
                for (int j = 0; j < 4; ++j) acc[i][j] += a[i] * bv[j];
        }
        __syncthreads();
    }
    #pragma unroll
    for (int i = 0; i < 4; ++i) {
        int b = rb + i;
        bool msk = (g_target[b] > tprev);
        size_t rowbase = ((size_t)b * TT + tprev) * VV;
        #pragma unroll
        for (int j = 0; j < 4; ++j) {
            int gn = n0 + cb + j;
            if (gn < VV) out[rowbase + gn] = msk ? (acc[i][j] + b_head[gn]) : 0.f;
        }
    }
}

__device__ __forceinline__ void dev_ctx(int b, int half, int t, SMu& sm,
        const float* __restrict__ b_gate, const float* __restrict__ emb,
        const int* __restrict__ tok, float* __restrict__ out_att) {
    int tid = threadIdx.x, lane = tid & 31, wid = tid >> 5;

    float v = (tid < PP) ? g_score[b * PP + tid] : -3.4e38f;
    float m = v;
    #pragma unroll
    for (int o = 16; o; o >>= 1) m = fmaxf(m, __shfl_xor_sync(0xffffffffu, m, o));
    if (lane == 0) sm.u.c.red[wid] = m;
    __syncthreads();
    if (tid == 0) {
        float mm = sm.u.c.red[0];
        #pragma unroll
        for (int i = 1; i < 8; ++i) mm = fmaxf(mm, sm.u.c.red[i]);
        sm.u.c.red[0] = mm;
    }
    __syncthreads();
    float mx = sm.u.c.red[0];
    __syncthreads();

    float e = (tid < PP) ? expf(v - mx) : 0.f;
    float s = e;
    #pragma unroll
    for (int o = 16; o; o >>= 1) s += __shfl_xor_sync(0xffffffffu, s, o);
    if (lane == 0) sm.u.c.red[wid] = s;
    __syncthreads();
    if (tid == 0) {
        float ss = 0.f;
        #pragma unroll
        for (int i = 0; i < 8; ++i) ss += sm.u.c.red[i];
        sm.u.c.red[0] = ss;
    }
    __syncthreads();
    float inv = 1.0f / sm.u.c.red[0];
    if (tid < PP) sm.u.c.sw[tid] = e * inv;
    __syncthreads();

    if (half == 0) {
        bool msk = (g_target[b] > t);
        if (tid < PP)
            out_att[((size_t)b * TT + t) * PP + tid] = msk ? sm.u.c.sw[tid] : 0.f;
        int token = tok[g_order[b] * LL + t];
        g_x[b * XK + tid] = emb[(size_t)token * EMB + tid];
        g_x[b * XK + EMB + EE + tid] = g_h[b * DD + tid];
    }

    int e0i = half * 1024 + tid * 4;
    const __half* fb = g_feat16 + (size_t)b * PP * EE + e0i;

    float4 s0 = make_float4(0.f, 0.f, 0.f, 0.f);
    float4 s1 = make_float4(0.f, 0.f, 0.f, 0.f);
    float4 s2 = make_float4(0.f, 0.f, 0.f, 0.f);
    float4 s3 = make_float4(0.f, 0.f, 0.f, 0.f);
    for (int p = 0; p < PP; p += 4) {
        float w0 = sm.u.c.sw[p], w1 = sm.u.c.sw[p + 1];
        float w2 = sm.u.c.sw[p + 2], w3 = sm.u.c.sw[p + 3];
        uint2 r0 = __ldcs((const uint2*)(fb + (size_t)(p + 0) * EE));
        uint2 r1 = __ldcs((const uint2*)(fb + (size_t)(p + 1) * EE));
        uint2 r2 = __ldcs((const uint2*)(fb + (size_t)(p + 2) * EE));
        uint2 r3 = __ldcs((const uint2*)(fb + (size_t)(p + 3) * EE));
        float2 a0 = __half22float2(*reinterpret_cast<__half2*>(&r0.x));
        float2 c0 = __half22float2(*reinterpret_cast<__half2*>(&r0.y));
        float2 a1 = __half22float2(*reinterpret_cast<__half2*>(&r1.x));
        float2 c1 = __half22float2(*reinterpret_cast<__half2*>(&r1.y));
        float2 a2 = __half22float2(*reinterpret_cast<__half2*>(&r2.x));
        float2 c2 = __half22float2(*reinterpret_cast<__half2*>(&r2.y));
        float2 a3 = __half22float2(*reinterpret_cast<__half2*>(&r3.x));
        float2 c3 = __half22float2(*reinterpret_cast<__half2*>(&r3.y));
        s0.x += w0 * a0.x; s0.y += w0 * a0.y; s0.z += w0 * c0.x; s0.w += w0 * c0.y;
        s1.x += w1 * a1.x; s1.y += w1 * a1.y; s1.z += w1 * c1.x; s1.w += w1 * c1.y;
        s2.x += w2 * a2.x; s2.y += w2 * a2.y; s2.z += w2 * c2.x; s2.w += w2 * c2.y;
        s3.x += w3 * a3.x; s3.y += w3 * a3.y; s3.z += w3 * c3.x; s3.w += w3 * c3.y;
    }
    float4 sum;
    sum.x = (s0.x + s1.x) + (s2.x + s3.x);
    sum.y = (s0.y + s1.y) + (s2.y + s3.y);
    sum.z = (s0.z + s1.z) + (s2.z + s3.z);
    sum.w = (s0.w + s1.w) + (s2.w + s3.w);

    float4 gp0 = *(const float4*)(g_gatep + (size_t)b * EE + e0i);
    float4 gp1 = *(const float4*)(g_gatep + ((size_t)NB + b) * EE + e0i);
    float4 bg  = *(const float4*)(b_gate + e0i);
    float4 ctx;
    ctx.x = sum.x * sigf(bg.x + gp0.x + gp1.x);
    ctx.y = sum.y * sigf(bg.y + gp0.y + gp1.y);
    ctx.z = sum.z * sigf(bg.z + gp0.z + gp1.z);
    ctx.w = sum.w * sigf(bg.w + gp0.w + gp1.w);
    *(float4*)(g_x + (size_t)b * XK + EMB + e0i) = ctx;
}

__device__ __forceinline__ void dev_gates(int nb, int kc, SMu& sm) {
    int tid = threadIdx.x;
    int k0g = kc * 256;
    const __half* wbase = g_Wih16 + (size_t)k0g * G4;
    float acc[4][4] = {};
    int rb = (tid >> 4) * 4, cb = (tid & 15) * 4;

    for (int kt = 0; kt < 256; kt += 16) {
        {
            int r = tid >> 2, kk = (tid & 3) * 4;
            float4 av = *(const float4*)(g_x + r * XK + k0g + kt + kk);
            sm.u.g.As[kk + 0][r] = av.x; sm.u.g.As[kk + 1][r] = av.y;
            sm.u.g.As[kk + 2][r] = av.z; sm.u.g.As[kk + 3][r] = av.w;
        }
        {
            int kk = tid >> 4, n = (tid & 15) * 4;
            const __half* src = wbase + (size_t)(kt + kk) * G4 + nb * 64 + n;
            float2 f0 = __half22float2(*(const __half2*)(src));
            float2 f1 = __half22float2(*(const __half2*)(src + 2));
            sm.u.g.Bs[kk][n + 0] = f0.x; sm.u.g.Bs[kk][n + 1] = f0.y;
            sm.u.g.Bs[kk][n + 2] = f1.x; sm.u.g.Bs[kk][n + 3] = f1.y;
        }
        __syncthreads();
        #pragma unroll
        for (int kk = 0; kk < 16; ++kk) {
            float a[4], bv[4];
            *(float4*)a  = *(float4*)&sm.u.g.As[kk][rb];
            *(float4*)bv = *(float4*)&sm.u.g.Bs[kk][cb];
            #pragma unroll
            for (int i = 0; i < 4; ++i)
                #pragma unroll
                for (int j = 0; j < 4; ++j) acc[i][j] += a[i] * bv[j];
        }
        __syncthreads();
    }
    #pragma unroll
    for (int i = 0; i < 4; ++i)
        #pragma unroll
        for (int j = 0; j < 4; ++j)
            g_gp[((size_t)kc * NB + rb + i) * G4 + nb * 64 + cb + j] = acc[i][j];
}

__device__ __forceinline__ void dev_lstm(int b, int t,
        const float* __restrict__ b_ih, const float* __restrict__ b_hh) {
    int j = threadIdx.x;
    float gi = b_ih[j] + b_hh[j];
    float gf = b_ih[DD + j] + b_hh[DD + j];
    float gg = b_ih[2 * DD + j] + b_hh[2 * DD + j];
    float go = b_ih[3 * DD + j] + b_hh[3 * DD + j];
    #pragma unroll
    for (int kc = 0; kc < KC; ++kc) {
        const float* p = g_gp + ((size_t)kc * NB + b) * G4;
        gi += p[j];
        gf += p[DD + j];
        gg += p[2 * DD + j];
        go += p[3 * DD + j];
    }
    float c = g_c[b * DD + j];
    float cn = sigf(gf) * c + sigf(gi) * tanhf(gg);
    float hn = sigf(go) * tanhf(cn);
    if (g_target[b] > t) {
        g_h[b * DD + j] = hn;
        g_c[b * DD + j] = cn;
    }
}

__global__ void __launch_bounds__(256, 2) k_loop(
        const float* __restrict__ Wh, const float* __restrict__ bh,
        const float* __restrict__ We, const float* __restrict__ be,
        const float* __restrict__ b_gate, const float* __restrict__ emb,
        const int* __restrict__ tok,
        const float* __restrict__ b_ih, const float* __restrict__ b_hh,
        const float* __restrict__ b_head,
        float* __restrict__ out, float* __restrict__ out_att) {
    __shared__ SMu sm;
    for (int t = 0; t < TT; ++t) {
        // Phase A: scores(t) 128 + gpre(t) 64 + head(t-1) nb[0,64) = 256 units
        int nA = 192 + (t >= 1 ? 64 : 0);
        for (int u = blockIdx.x; u < nA; u += NBLK) {
            __syncthreads();
            if (u < 128)      dev_score(u >> 1, u & 1, sm, Wh, bh, We, be);
            else if (u < 192) dev_gpre(u - 128, sm);
            else              dev_head(u - 192, t - 1, sm, b_head, out);
        }
        gridbar();
        // Phase B: ctx 128 + head(t-1) nb[64,157) = 221 units
        int nB = 128 + (t >= 1 ? 93 : 0);
        for (int u = blockIdx.x; u < nB; u += NBLK) {
            __syncthreads();
            if (u < 128) dev_ctx(u >> 1, u & 1, t, sm, b_gate, emb, tok, out_att);
            else         dev_head(64 + (u - 128), t - 1, sm, b_head, out);
        }
        gridbar();
        // Phase C: gates split-K GEMM (160 units)
        for (int u = blockIdx.x; u < 160; u += NBLK) {
            __syncthreads();
            dev_gates(u & 15, u >> 4, sm);
        }
        gridbar();
        // Phase D: LSTM pointwise (64 units)
        if (blockIdx.x < NB) dev_lstm(blockIdx.x, t, b_ih, b_hh);
        gridbar();
    }
    // Tail: head for the final step (t = TT-1)
    for (int u = blockIdx.x; u < 157; u += NBLK) {
        __syncthreads();
        dev_head(u, TT - 1, sm, b_head, out);
    }
}

// ---------------------------------------------------------------------------
extern "C" void kernel_launch(void* const* d_in, const int* in_sizes, int n_in,
                              void* d_out, int out_size) {
    const float* feat   = (const float*)d_in[0];
    const int*   tok    = (const int*)d_in[1];
    const int*   caplen = (const int*)d_in[2];
    const float* Wf     = (const float*)d_in[3];
    const float* bf     = (const float*)d_in[4];
    const float* Wh     = (const float*)d_in[5];
    const float* bh     = (const float*)d_in[6];
    const float* We     = (const float*)d_in[7];
    const float* be     = (const float*)d_in[8];
    const float* emb    = (const float*)d_in[9];
    const float* W_ih   = (const float*)d_in[10];
    const float* b_ih   = (const float*)d_in[11];
    const float* W_hh   = (const float*)d_in[12];
    const float* b_hh   = (const float*)d_in[13];
    const float* W_hid  = (const float*)d_in[14];
    const float* b_hid  = (const float*)d_in[15];
    const float* W_cell = (const float*)d_in[16];
    const float* b_cell = (const float*)d_in[17];
    const float* W_gate = (const float*)d_in[18];
    const float* b_gate = (const float*)d_in[19];
    const float* W_head = (const float*)d_in[20];
    const float* b_head = (const float*)d_in[21];

    float* out = (float*)d_out;
    float* out_att = out + (size_t)NB * TT * VV;

    k_order<<<1, 32>>>(caplen);
    k_cvt<<<512, 256>>>(W_gate, W_ih, W_hh, W_head);
    k_cvtf<<<NB * PP, 256>>>(feat);
    k_fe<<<dim3(98, 5), 256>>>(feat, Wf, bf);     // fe GEMM (fp16 A/out) + mean
    k_initA<<<dim3(8, 8), 256>>>(W_hid, W_cell);  // init GEMM, split-K
    k_init2<<<NB, 256>>>(b_hid, b_cell);

    // entire 31-step decoder loop in ONE persistent kernel
    k_loop<<<NBLK, 256>>>(Wh, bh, We, be, b_gate, emb, tok,
                          b_ih, b_hh, b_head, out, out_att);
}

// round 10
// speedup vs baseline: 1.4922x; 1.1062x over previous
#include <cuda_runtime.h>
#include <cuda_fp16.h>
#include <cstdint>

static constexpr int NB  = 64;     // batch
static constexpr int PP  = 196;    // spatial positions
static constexpr int EE  = 2048;   // feature dim
static constexpr int DD  = 256;    // hidden
static constexpr int HH  = 256;    // attention hidden
static constexpr int EMB = 256;    // embedding
static constexpr int VV  = 10000;  // vocab
static constexpr int LL  = 32;     // caption length
static constexpr int TT  = 31;     // timesteps
static constexpr int XK  = EMB + EE + DD;  // 2560
static constexpr int G4  = 4 * DD;         // 1024
static constexpr int KC  = 10;             // split-K chunks for gates gemm
static constexpr int NBLK = 256;           // persistent grid size

__device__ int    g_order[NB];
__device__ int    g_target[NB];
__device__ int    g_nact[TT + 1];           // active rows (target > t) per step
__device__ __half g_feat16[NB * PP * EE];   // 51.4 MB fp16 feat, order-permuted
__device__ __half g_fe16[NB * PP * HH];     // 6.4 MB fp16 attention features
__device__ float  g_mean[NB * EE];
__device__ float  g_h[NB * DD];
__device__ float  g_c[NB * DD];
__device__ float  g_score[NB * PP];
__device__ float  g_x[NB * XK];
__device__ float  g_gp[KC * NB * G4];       // split-K partials (gates / init)
__device__ float  g_gatep[2 * NB * EE];     // split-K partials for gate pre-act
__device__ __half g_Wg16[DD * EE];          // W_gate fp16
__device__ __half g_Wih16[XK * G4];         // [W_ih ; W_hh] fp16 concat
__device__ __half g_Whead16[DD * VV];       // W_head fp16
__device__ __half g_Wf16[EE * HH];          // Wf fp16 (same [K,N] layout)

// software grid barrier state
__device__ int          g_bar_count;
__device__ volatile int g_bar_gen;

__device__ __forceinline__ float sigf(float x) { return 1.0f / (1.0f + expf(-x)); }

// ---------------------------------------------------------------------------
// K0: stable descending counting sort + per-step active counts
// ---------------------------------------------------------------------------
__global__ void k_order(const int* __restrict__ caplen) {
    if (threadIdx.x == 0) {
        int idx = 0;
        for (int v = LL; v >= 1; --v) {
            for (int i = 0; i < NB; ++i) {
                if (caplen[i] == v) {
                    g_order[idx]  = i;
                    g_target[idx] = v - 1;
                    ++idx;
                }
            }
        }
        for (int t = 0; t <= TT; ++t) {
            int n = 0;
            for (int i = 0; i < NB; ++i) n += (g_target[i] > t) ? 1 : 0;
            g_nact[t] = n;
        }
    }
}

// ---------------------------------------------------------------------------
// K_cvt: one-time fp32 -> fp16 conversion of weights (incl. Wf)
// ---------------------------------------------------------------------------
__global__ void k_cvt(const float* __restrict__ Wg, const float* __restrict__ Wih,
                      const float* __restrict__ Whh, const float* __restrict__ Whead,
                      const float* __restrict__ Wf) {
    const int NQ_G  = (DD * EE) / 4;
    const int NQ_IH = (2304 * G4) / 4;
    const int NQ_HH = (DD * G4) / 4;
    const int NQ_HD = (DD * VV) / 4;
    const int NQ_WF = (EE * HH) / 4;
    const int total = NQ_G + NQ_IH + NQ_HH + NQ_HD + NQ_WF;
    for (int i = blockIdx.x * blockDim.x + threadIdx.x; i < total;
         i += gridDim.x * blockDim.x) {
        const float* src; __half* dst; int q;
        if (i < NQ_G)                          { src = Wg;    dst = g_Wg16;              q = i; }
        else if (i < NQ_G + NQ_IH)             { src = Wih;   dst = g_Wih16;             q = i - NQ_G; }
        else if (i < NQ_G + NQ_IH + NQ_HH)     { src = Whh;  dst = g_Wih16 + 2304 * G4;  q = i - NQ_G - NQ_IH; }
        else if (i < NQ_G + NQ_IH + NQ_HH + NQ_HD) { src = Whead; dst = g_Whead16;       q = i - NQ_G - NQ_IH - NQ_HH; }
        else                                   { src = Wf;    dst = g_Wf16;              q = i - NQ_G - NQ_IH - NQ_HH - NQ_HD; }
        float4 v = *(const float4*)(src + (size_t)q * 4);
        *(__half2*)(dst + (size_t)q * 4)     = __floats2half2_rn(v.x, v.y);
        *(__half2*)(dst + (size_t)q * 4 + 2) = __floats2half2_rn(v.z, v.w);
    }
}

// ---------------------------------------------------------------------------
// K_cvtf: one-time feat -> fp16 with the order permutation baked in.
// ---------------------------------------------------------------------------
__global__ void __launch_bounds__(256) k_cvtf(const float* __restrict__ feat) {
    int row = blockIdx.x;
    int b = row / PP, p = row % PP;
    const float* src = feat + ((size_t)g_order[b] * PP + p) * EE + threadIdx.x * 8;
    __half* dst = g_feat16 + (size_t)row * EE + threadIdx.x * 8;
    float4 v0 = *(const float4*)(src);
    float4 v1 = *(const float4*)(src + 4);
    *(__half2*)(dst + 0) = __floats2half2_rn(v0.x, v0.y);
    *(__half2*)(dst + 2) = __floats2half2_rn(v0.z, v0.w);
    *(__half2*)(dst + 4) = __floats2half2_rn(v1.x, v1.y);
    *(__half2*)(dst + 6) = __floats2half2_rn(v1.z, v1.w);
}

// ---------------------------------------------------------------------------
// K3: grid (98, 5).  y<4: fe = feat16 @ Wf16 + bf via mma.sync (tensor cores).
//     BM=128, BN=64, BK=64; 8 warps in 4(m) x 2(n); each warp 32x32 out.
//     y==4: mean over positions from fp32 feat (blocks 0..63).
// ---------------------------------------------------------------------------
__global__ void __launch_bounds__(256) k_fe(const float* __restrict__ feat,
                                            const float* __restrict__ bf) {
    int tid = threadIdx.x;
    int mb = blockIdx.x, nb = blockIdx.y;

    if (nb == 4) {
        if (mb >= NB) return;
        int b = mb;
        const float4* base = (const float4*)(feat + (size_t)g_order[b] * PP * EE);
        float4 sA = make_float4(0.f, 0.f, 0.f, 0.f);
        float4 sB = make_float4(0.f, 0.f, 0.f, 0.f);
        #pragma unroll 2
        for (int p = 0; p < PP; ++p) {
            float4 v0 = __ldcs(base + (size_t)p * (EE / 4) + tid);
            float4 v1 = __ldcs(base + (size_t)p * (EE / 4) + tid + 256);
            sA.x += v0.x; sA.y += v0.y; sA.z += v0.z; sA.w += v0.w;
            sB.x += v1.x; sB.y += v1.y; sB.z += v1.z; sB.w += v1.w;
        }
        const float inv = 1.0f / PP;
        sA.x *= inv; sA.y *= inv; sA.z *= inv; sA.w *= inv;
        sB.x *= inv; sB.y *= inv; sB.z *= inv; sB.w *= inv;
        *(float4*)(g_mean + b * EE + tid * 4)        = sA;
        *(float4*)(g_mean + b * EE + 1024 + tid * 4) = sB;
        return;
    }

    __shared__ __half As[128][72];   // 72-pad -> conflict-free ldmatrix
    __shared__ __half Bs[64][72];

    int warp = tid >> 5, lane = tid & 31;
    int wm = warp & 3, wn = warp >> 2;         // warp tile: rows wm*32, cols wn*32

    float acc[2][4][4] = {};                   // [mi 16][ni 8][4]

    for (int k0 = 0; k0 < EE; k0 += 64) {
        #pragma unroll
        for (int i = 0; i < 4; ++i) {
            int idx = tid + i * 256;           // 1024 uint4 for A (128x64 halves)
            int r = idx >> 3, c = (idx & 7) * 8;
            *(uint4*)&As[r][c] =
                *(const uint4*)(g_feat16 + (size_t)(mb * 128 + r) * EE + k0 + c);
        }
        #pragma unroll
        for (int i = 0; i < 2; ++i) {
            int idx = tid + i * 256;           // 512 uint4 for B (64x64 halves)
            int r = idx >> 3, c = (idx & 7) * 8;
            *(uint4*)&Bs[r][c] =
                *(const uint4*)(g_Wf16 + (size_t)(k0 + r) * HH + nb * 64 + c);
        }
        __syncthreads();

        #pragma unroll
        for (int kk = 0; kk < 64; kk += 16) {
            unsigned a[2][4], b[4][2];
            #pragma unroll
            for (int mi = 0; mi < 2; ++mi) {
                unsigned addr = (unsigned)__cvta_generic_to_shared(
                    &As[wm * 32 + mi * 16 + (lane & 15)][kk + (lane >> 4) * 8]);
                asm volatile("ldmatrix.sync.aligned.m8n8.x4.shared.b16 {%0,%1,%2,%3}, [%4];"
                    : "=r"(a[mi][0]), "=r"(a[mi][1]), "=r"(a[mi][2]), "=r"(a[mi][3])
                    : "r"(addr));
            }
            #pragma unroll
            for (int ni = 0; ni < 4; ++ni) {
                unsigned addr = (unsigned)__cvta_generic_to_shared(
                    &Bs[kk + (lane & 15)][wn * 32 + ni * 8]);
                asm volatile("ldmatrix.sync.aligned.m8n8.x2.trans.shared.b16 {%0,%1}, [%2];"
                    : "=r"(b[ni][0]), "=r"(b[ni][1]) : "r"(addr));
            }
            #pragma unroll
            for (int mi = 0; mi < 2; ++mi)
                #pragma unroll
                for (int ni = 0; ni < 4; ++ni)
                    asm volatile(
                        "mma.sync.aligned.m16n8k16.row.col.f32.f16.f16.f32 "
                        "{%0,%1,%2,%3}, {%4,%5,%6,%7}, {%8,%9}, {%0,%1,%2,%3};"
                        : "+f"(acc[mi][ni][0]), "+f"(acc[mi][ni][1]),
                          "+f"(acc[mi][ni][2]), "+f"(acc[mi][ni][3])
                        : "r"(a[mi][0]), "r"(a[mi][1]), "r"(a[mi][2]), "r"(a[mi][3]),
                          "r"(b[ni][0]), "r"(b[ni][1]));
        }
        __syncthreads();
    }

    int gr = lane >> 2;          // 0..7
    int gc = (lane & 3) * 2;     // 0,2,4,6
    #pragma unroll
    for (int mi = 0; mi < 2; ++mi)
        #pragma unroll
        for (int ni = 0; ni < 4; ++ni) {
            int gn = nb * 64 + wn * 32 + ni * 8 + gc;
            float b0 = bf[gn], b1 = bf[gn + 1];
            int m0 = mb * 128 + wm * 32 + mi * 16 + gr;
            *(__half2*)(g_fe16 + (size_t)m0 * HH + gn) =
                __floats2half2_rn(acc[mi][ni][0] + b0, acc[mi][ni][1] + b1);
            int m1 = m0 + 8;
            *(__half2*)(g_fe16 + (size_t)m1 * HH + gn) =
                __floats2half2_rn(acc[mi][ni][2] + b0, acc[mi][ni][3] + b1);
        }
}

// ---------------------------------------------------------------------------
// K2a: init GEMM  mean(64x2048) @ [W_hid | W_cell](2048x512), split-K=8.
// ---------------------------------------------------------------------------
__global__ void __launch_bounds__(256) k_initA(const float* __restrict__ W_hid,
                                               const float* __restrict__ W_cell) {
    __shared__ float As[16][68];
    __shared__ float Bs[16][64];
    int tid = threadIdx.x;
    int nb = blockIdx.x, kc = blockIdx.y;
    const float* wsrc = (nb < 4) ? W_hid : W_cell;
    int ncol0 = (nb & 3) * 64;
    int k0g = kc * 256;
    float acc[4][4] = {};
    int rb = (tid >> 4) * 4, cb = (tid & 15) * 4;

    for (int kt = 0; kt < 256; kt += 16) {
        {
            int r = tid >> 2, kk = (tid & 3) * 4;
            float4 av = *(const float4*)(g_mean + r * EE + k0g + kt + kk);
            As[kk + 0][r] = av.x; As[kk + 1][r] = av.y;
            As[kk + 2][r] = av.z; As[kk + 3][r] = av.w;
        }
        {
            int kk = tid >> 4, n = (tid & 15) * 4;
            *(float4*)&Bs[kk][n] =
                *(const float4*)(wsrc + (size_t)(k0g + kt + kk) * DD + ncol0 + n);
        }
        __syncthreads();
        #pragma unroll
        for (int kk = 0; kk < 16; ++kk) {
            float a[4], bv[4];
            *(float4*)a  = *(float4*)&As[kk][rb];
            *(float4*)bv = *(float4*)&Bs[kk][cb];
            #pragma unroll
            for (int i = 0; i < 4; ++i)
                #pragma unroll
                for (int j = 0; j < 4; ++j) acc[i][j] += a[i] * bv[j];
        }
        __syncthreads();
    }
    #pragma unroll
    for (int i = 0; i < 4; ++i)
        #pragma unroll
        for (int j = 0; j < 4; ++j)
            g_gp[((size_t)kc * NB + rb + i) * 512 + nb * 64 + cb + j] = acc[i][j];
}

__global__ void k_init2(const float* __restrict__ b_hid, const float* __restrict__ b_cell) {
    int b = blockIdx.x, j = threadIdx.x;
    float h = b_hid[j], c = b_cell[j];
    #pragma unroll
    for (int kc = 0; kc < 8; ++kc) {
        const float* p = g_gp + ((size_t)kc * NB + b) * 512;
        h += p[j];
        c += p[256 + j];
    }
    g_h[b * DD + j] = h;
    g_c[b * DD + j] = c;
}

// ===========================================================================
// Persistent step-loop kernel
// ===========================================================================
struct SMu {
    union {
        struct { float As[16][68]; float Bs[16][64]; } g;
        struct { float sh[256]; float she[256]; float swe[256]; } a;
        struct { float sw[256]; float red[8]; } c;
    } u;
};

__device__ __forceinline__ void gridbar() {
    __syncthreads();
    __threadfence();
    if (threadIdx.x == 0) {
        int gen = g_bar_gen;
        if (atomicAdd(&g_bar_count, 1) == NBLK - 1) {
            g_bar_count = 0;
            __threadfence();
            g_bar_gen = gen + 1;
        } else {
            while (g_bar_gen == gen) __nanosleep(64);
        }
    }
    __syncthreads();
    __threadfence();
}

__device__ __forceinline__ void dev_score(int b, int half, SMu& sm,
        const float* __restrict__ Wh, const float* __restrict__ bh,
        const float* __restrict__ We, const float* __restrict__ be) {
    int tid = threadIdx.x, lane = tid & 31, wid = tid >> 5;
    sm.u.a.sh[tid]  = g_h[b * DD + tid];
    sm.u.a.swe[tid] = We[tid];
    __syncthreads();
    float acc = bh[tid];
    #pragma unroll 8
    for (int k = 0; k < DD; ++k) acc += sm.u.a.sh[k] * Wh[k * HH + tid];
    sm.u.a.she[tid] = acc;
    __syncthreads();
    float be0 = be[0];
    int p0 = half * 98, p1 = p0 + 98;
    const __half* febase = g_fe16 + (size_t)b * PP * HH;
    for (int p = p0 + wid; p < p1; p += 8) {
        const __half* fr = febase + (size_t)p * HH;
        float s = 0.f;
        #pragma unroll
        for (int it = 0; it < 4; ++it) {
            int j = it * 64 + lane * 2;
            float2 fv = __half22float2(*(const __half2*)(fr + j));
            float v0 = fv.x + sm.u.a.she[j], v1 = fv.y + sm.u.a.she[j + 1];
            s += fmaxf(v0, 0.f) * sm.u.a.swe[j] + fmaxf(v1, 0.f) * sm.u.a.swe[j + 1];
        }
        #pragma unroll
        for (int o = 16; o; o >>= 1) s += __shfl_xor_sync(0xffffffffu, s, o);
        if (lane == 0) g_score[b * PP + p] = s + be0;
    }
}

__device__ __forceinline__ void dev_gpre(int bid, SMu& sm) {
    int tid = threadIdx.x;
    int nb = bid & 31, kc = bid >> 5;
    int kbase = kc * 128;
    float acc[4][4] = {};
    int rb = (tid >> 4) * 4, cb = (tid & 15) * 4;

    for (int kt = 0; kt < 128; kt += 16) {
        {
            int r = tid >> 2, kk = (tid & 3) * 4;
            float4 av = *(const float4*)(g_h + r * DD + kbase + kt + kk);
            sm.u.g.As[kk + 0][r] = av.x; sm.u.g.As[kk + 1][r] = av.y;
            sm.u.g.As[kk + 2][r] = av.z; sm.u.g.As[kk + 3][r] = av.w;
        }
        {
            int kk = tid >> 4, n = (tid & 15) * 4;
            const __half* src = g_Wg16 + (size_t)(kbase + kt + kk) * EE + nb * 64 + n;
            float2 f0 = __half22float2(*(const __half2*)(src));
            float2 f1 = __half22float2(*(const __half2*)(src + 2));
            sm.u.g.Bs[kk][n + 0] = f0.x; sm.u.g.Bs[kk][n + 1] = f0.y;
            sm.u.g.Bs[kk][n + 2] = f1.x; sm.u.g.Bs[kk][n + 3] = f1.y;
        }
        __syncthreads();
        #pragma unroll
        for (int kk = 0; kk < 16; ++kk) {
            float a[4], bv[4];
            *(float4*)a  = *(float4*)&sm.u.g.As[kk][rb];
            *(float4*)bv = *(float4*)&sm.u.g.Bs[kk][cb];
            #pragma unroll
            for (int i = 0; i < 4; ++i)
                #pragma unroll
                for (int j = 0; j < 4; ++j) acc[i][j] += a[i] * bv[j];
        }
        __syncthreads();
    }
    #pragma unroll
    for (int i = 0; i < 4; ++i)
        #pragma unroll
        for (int j = 0; j < 4; ++j)
            g_gatep[((size_t)kc * NB + rb + i) * EE + nb * 64 + cb + j] = acc[i][j];
}

__device__ __forceinline__ void dev_head(int nb, int tprev, SMu& sm,
        const float* __restrict__ b_head, float* __restrict__ out) {
    int tid = threadIdx.x;
    int n0 = nb * 64;
    float acc[4][4] = {};
    int rb = (tid >> 4) * 4, cb = (tid & 15) * 4;

    for (int k0 = 0; k0 < DD; k0 += 16) {
        {
            int r = tid >> 2, kk = (tid & 3) * 4;
            float4 av = *(const float4*)(g_h + r * DD + k0 + kk);
            sm.u.g.As[kk + 0][r] = av.x; sm.u.g.As[kk + 1][r] = av.y;
            sm.u.g.As[kk + 2][r] = av.z; sm.u.g.As[kk + 3][r] = av.w;
        }
        {
            int kk = tid >> 4, n = (tid & 15) * 4;
            int gn = n0 + n;
            const __half* src = g_Whead16 + (size_t)(k0 + kk) * VV + gn;
            float b0, b1, b2, b3;
            if (gn + 3 < VV) {
                float2 f0 = __half22float2(*(const __half2*)(src));
                float2 f1 = __half22float2(*(const __half2*)(src + 2));
                b0 = f0.x; b1 = f0.y; b2 = f1.x; b3 = f1.y;
            } else {
                b0 = (gn + 0 < VV) ? __half2float(src[0]) : 0.f;
                b1 = (gn + 1 < VV) ? __half2float(src[1]) : 0.f;
                b2 = (gn + 2 < VV) ? __half2float(src[2]) : 0.f;
                b3 = (gn + 3 < VV) ? __half2float(src[3]) : 0.f;
            }
            sm.u.g.Bs[kk][n + 0] = b0; sm.u.g.Bs[kk][n + 1] = b1;
            sm.u.g.Bs[kk][n + 2] = b2; sm.u.g.Bs[kk][n + 3] = b3;
        }
        __syncthreads();
        #pragma unroll
        for (int kk = 0; kk < 16; ++kk) {
            float a[4], bv[4];
            *(float4*)a  = *(float4*)&sm.u.g.As[kk][rb];
            *(float4*)bv = *(float4*)&sm.u.g.Bs[kk][cb];
            #pragma unroll
            for (int i = 0; i < 4; ++i)
                #pragma unroll
                for (int j = 0; j < 4; ++j) acc[i][j] += a[i] * bv[j];
        }
        __syncthreads();
    }
    #pragma unroll
    for (int i = 0; i < 4; ++i) {
        int b = rb + i;
        bool msk = (g_target[b] > tprev);
        size_t rowbase = ((size_t)b * TT + tprev) * VV;
        #pragma unroll
        for (int j = 0; j < 4; ++j) {
            int gn = n0 + cb + j;
            if (gn < VV) out[rowbase + gn] = msk ? (acc[i][j] + b_head[gn]) : 0.f;
        }
    }
}

__device__ __forceinline__ void dev_ctx(int b, int half, int t, int nact, SMu& sm,
        const float* __restrict__ b_gate, const float* __restrict__ emb,
        const int* __restrict__ tok, float* __restrict__ out_att) {
    int tid = threadIdx.x, lane = tid & 31, wid = tid >> 5;

    if (b >= nact) {
        // inactive row: outputs masked to zero; h/c frozen; stale x is harmless
        if (half == 0 && tid < PP)
            out_att[((size_t)b * TT + t) * PP + tid] = 0.f;
        return;
    }

    float v = (tid < PP) ? g_score[b * PP + tid] : -3.4e38f;
    float m = v;
    #pragma unroll
    for (int o = 16; o; o >>= 1) m = fmaxf(m, __shfl_xor_sync(0xffffffffu, m, o));
    if (lane == 0) sm.u.c.red[wid] = m;
    __syncthreads();
    if (tid == 0) {
        float mm = sm.u.c.red[0];
        #pragma unroll
        for (int i = 1; i < 8; ++i) mm = fmaxf(mm, sm.u.c.red[i]);
        sm.u.c.red[0] = mm;
    }
    __syncthreads();
    float mx = sm.u.c.red[0];
    __syncthreads();

    float e = (tid < PP) ? expf(v - mx) : 0.f;
    float s = e;
    #pragma unroll
    for (int o = 16; o; o >>= 1) s += __shfl_xor_sync(0xffffffffu, s, o);
    if (lane == 0) sm.u.c.red[wid] = s;
    __syncthreads();
    if (tid == 0) {
        float ss = 0.f;
        #pragma unroll
        for (int i = 0; i < 8; ++i) ss += sm.u.c.red[i];
        sm.u.c.red[0] = ss;
    }
    __syncthreads();
    float inv = 1.0f / sm.u.c.red[0];
    if (tid < PP) sm.u.c.sw[tid] = e * inv;
    __syncthreads();

    if (half == 0) {
        if (tid < PP)
            out_att[((size_t)b * TT + t) * PP + tid] = sm.u.c.sw[tid];
        int token = tok[g_order[b] * LL + t];
        g_x[b * XK + tid] = emb[(size_t)token * EMB + tid];
        g_x[b * XK + EMB + EE + tid] = g_h[b * DD + tid];
    }

    int e0i = half * 1024 + tid * 4;
    const __half* fb = g_feat16 + (size_t)b * PP * EE + e0i;

    float4 s0 = make_float4(0.f, 0.f, 0.f, 0.f);
    float4 s1 = make_float4(0.f, 0.f, 0.f, 0.f);
    float4 s2 = make_float4(0.f, 0.f, 0.f, 0.f);
    float4 s3 = make_float4(0.f, 0.f, 0.f, 0.f);
    for (int p = 0; p < PP; p += 4) {
        float w0 = sm.u.c.sw[p], w1 = sm.u.c.sw[p + 1];
        float w2 = sm.u.c.sw[p + 2], w3 = sm.u.c.sw[p + 3];
        uint2 r0 = __ldcs((const uint2*)(fb + (size_t)(p + 0) * EE));
        uint2 r1 = __ldcs((const uint2*)(fb + (size_t)(p + 1) * EE));
        uint2 r2 = __ldcs((const uint2*)(fb + (size_t)(p + 2) * EE));
        uint2 r3 = __ldcs((const uint2*)(fb + (size_t)(p + 3) * EE));
        float2 a0 = __half22float2(*reinterpret_cast<__half2*>(&r0.x));
        float2 c0 = __half22float2(*reinterpret_cast<__half2*>(&r0.y));
        float2 a1 = __half22float2(*reinterpret_cast<__half2*>(&r1.x));
        float2 c1 = __half22float2(*reinterpret_cast<__half2*>(&r1.y));
        float2 a2 = __half22float2(*reinterpret_cast<__half2*>(&r2.x));
        float2 c2 = __half22float2(*reinterpret_cast<__half2*>(&r2.y));
        float2 a3 = __half22float2(*reinterpret_cast<__half2*>(&r3.x));
        float2 c3 = __half22float2(*reinterpret_cast<__half2*>(&r3.y));
        s0.x += w0 * a0.x; s0.y += w0 * a0.y; s0.z += w0 * c0.x; s0.w += w0 * c0.y;
        s1.x += w1 * a1.x; s1.y += w1 * a1.y; s1.z += w1 * c1.x; s1.w += w1 * c1.y;
        s2.x += w2 * a2.x; s2.y += w2 * a2.y; s2.z += w2 * c2.x; s2.w += w2 * c2.y;
        s3.x += w3 * a3.x; s3.y += w3 * a3.y; s3.z += w3 * c3.x; s3.w += w3 * c3.y;
    }
    float4 sum;
    sum.x = (s0.x + s1.x) + (s2.x + s3.x);
    sum.y = (s0.y + s1.y) + (s2.y + s3.y);
    sum.z = (s0.z + s1.z) + (s2.z + s3.z);
    sum.w = (s0.w + s1.w) + (s2.w + s3.w);

    float4 gp0 = *(const float4*)(g_gatep + (size_t)b * EE + e0i);
    float4 gp1 = *(const float4*)(g_gatep + ((size_t)NB + b) * EE + e0i);
    float4 bg  = *(const float4*)(b_gate + e0i);
    float4 ctx;
    ctx.x = sum.x * sigf(bg.x + gp0.x + gp1.x);
    ctx.y = sum.y * sigf(bg.y + gp0.y + gp1.y);
    ctx.z = sum.z * sigf(bg.z + gp0.z + gp1.z);
    ctx.w = sum.w * sigf(bg.w + gp0.w + gp1.w);
    *(float4*)(g_x + (size_t)b * XK + EMB + e0i) = ctx;
}

__device__ __forceinline__ void dev_gates(int nb, int kc, SMu& sm) {
    int tid = threadIdx.x;
    int k0g = kc * 256;
    const __half* wbase = g_Wih16 + (size_t)k0g * G4;
    float acc[4][4] = {};
    int rb = (tid >> 4) * 4, cb = (tid & 15) * 4;

    for (int kt = 0; kt < 256; kt += 16) {
        {
            int r = tid >> 2, kk = (tid & 3) * 4;
            float4 av = *(const float4*)(g_x + r * XK + k0g + kt + kk);
            sm.u.g.As[kk + 0][r] = av.x; sm.u.g.As[kk + 1][r] = av.y;
            sm.u.g.As[kk + 2][r] = av.z; sm.u.g.As[kk + 3][r] = av.w;
        }
        {
            int kk = tid >> 4, n = (tid & 15) * 4;
            const __half* src = wbase + (size_t)(kt + kk) * G4 + nb * 64 + n;
            float2 f0 = __half22float2(*(const __half2*)(src));
            float2 f1 = __half22float2(*(const __half2*)(src + 2));
            sm.u.g.Bs[kk][n + 0] = f0.x; sm.u.g.Bs[kk][n + 1] = f0.y;
            sm.u.g.Bs[kk][n + 2] = f1.x; sm.u.g.Bs[kk][n + 3] = f1.y;
        }
        __syncthreads();
        #pragma unroll
        for (int kk = 0; kk < 16; ++kk) {
            float a[4], bv[4];
            *(float4*)a  = *(float4*)&sm.u.g.As[kk][rb];
            *(float4*)bv = *(float4*)&sm.u.g.Bs[kk][cb];
            #pragma unroll
            for (int i = 0; i < 4; ++i)
                #pragma unroll
                for (int j = 0; j < 4; ++j) acc[i][j] += a[i] * bv[j];
        }
        __syncthreads();
    }
    #pragma unroll
    for (int i = 0; i < 4; ++i)
        #pragma unroll
        for (int j = 0; j < 4; ++j)
            g_gp[((size_t)kc * NB + rb + i) * G4 + nb * 64 + cb + j] = acc[i][j];
}

__device__ __forceinline__ void dev_lstm(int b, int t,
        const float* __restrict__ b_ih, const float* __restrict__ b_hh) {
    int j = threadIdx.x;
    float gi = b_ih[j] + b_hh[j];
    float gf = b_ih[DD + j] + b_hh[DD + j];
    float gg = b_ih[2 * DD + j] + b_hh[2 * DD + j];
    float go = b_ih[3 * DD + j] + b_hh[3 * DD + j];
    #pragma unroll
    for (int kc = 0; kc < KC; ++kc) {
        const float* p = g_gp + ((size_t)kc * NB + b) * G4;
        gi += p[j];
        gf += p[DD + j];
        gg += p[2 * DD + j];
        go += p[3 * DD + j];
    }
    float c = g_c[b * DD + j];
    float cn = sigf(gf) * c + sigf(gi) * tanhf(gg);
    float hn = sigf(go) * tanhf(cn);
    if (g_target[b] > t) {
        g_h[b * DD + j] = hn;
        g_c[b * DD + j] = cn;
    }
}

__global__ void __launch_bounds__(256, 2) k_loop(
        const float* __restrict__ Wh, const float* __restrict__ bh,
        const float* __restrict__ We, const float* __restrict__ be,
        const float* __restrict__ b_gate, const float* __restrict__ emb,
        const int* __restrict__ tok,
        const float* __restrict__ b_ih, const float* __restrict__ b_hh,
        const float* __restrict__ b_head,
        float* __restrict__ out, float* __restrict__ out_att) {
    __shared__ SMu sm;
    for (int t = 0; t < TT; ++t) {
        int nact = g_nact[t];
        // Phase A: scores(t) 128 + gpre(t) 64 + head(t-1) nb[0,64) = 256 units
        int nA = 192 + (t >= 1 ? 64 : 0);
        for (int u = blockIdx.x; u < nA; u += NBLK) {
            __syncthreads();
            if (u < 128) {
                if ((u >> 1) < nact) dev_score(u >> 1, u & 1, sm, Wh, bh, We, be);
            }
            else if (u < 192) dev_gpre(u - 128, sm);
            else              dev_head(u - 192, t - 1, sm, b_head, out);
        }
        gridbar();
        // Phase B: ctx 128 + head(t-1) nb[64,157) = 221 units
        int nB = 128 + (t >= 1 ? 93 : 0);
        for (int u = blockIdx.x; u < nB; u += NBLK) {
            __syncthreads();
            if (u < 128) dev_ctx(u >> 1, u & 1, t, nact, sm, b_gate, emb, tok, out_att);
            else         dev_head(64 + (u - 128), t - 1, sm, b_head, out);
        }
        gridbar();
        // Phase C: gates split-K GEMM (160 units)
        for (int u = blockIdx.x; u < 160; u += NBLK) {
            __syncthreads();
            dev_gates(u & 15, u >> 4, sm);
        }
        gridbar();
        // Phase D: LSTM pointwise (64 units)
        if (blockIdx.x < NB) dev_lstm(blockIdx.x, t, b_ih, b_hh);
        gridbar();
    }
    // Tail: head for the final step (t = TT-1)
    for (int u = blockIdx.x; u < 157; u += NBLK) {
        __syncthreads();
        dev_head(u, TT - 1, sm, b_head, out);
    }
}

// ---------------------------------------------------------------------------
extern "C" void kernel_launch(void* const* d_in, const int* in_sizes, int n_in,
                              void* d_out, int out_size) {
    const float* feat   = (const float*)d_in[0];
    const int*   tok    = (const int*)d_in[1];
    const int*   caplen = (const int*)d_in[2];
    const float* Wf     = (const float*)d_in[3];
    const float* bf     = (const float*)d_in[4];
    const float* Wh     = (const float*)d_in[5];
    const float* bh     = (const float*)d_in[6];
    const float* We     = (const float*)d_in[7];
    const float* be     = (const float*)d_in[8];
    const float* emb    = (const float*)d_in[9];
    const float* W_ih   = (const float*)d_in[10];
    const float* b_ih   = (const float*)d_in[11];
    const float* W_hh   = (const float*)d_in[12];
    const float* b_hh   = (const float*)d_in[13];
    const float* W_hid  = (const float*)d_in[14];
    const float* b_hid  = (const float*)d_in[15];
    const float* W_cell = (const float*)d_in[16];
    const float* b_cell = (const float*)d_in[17];
    const float* W_gate = (const float*)d_in[18];
    const float* b_gate = (const float*)d_in[19];
    const float* W_head = (const float*)d_in[20];
    const float* b_head = (const float*)d_in[21];

    float* out = (float*)d_out;
    float* out_att = out + (size_t)NB * TT * VV;

    k_order<<<1, 32>>>(caplen);
    k_cvt<<<512, 256>>>(W_gate, W_ih, W_hh, W_head, Wf);
    k_cvtf<<<NB * PP, 256>>>(feat);
    k_fe<<<dim3(98, 5), 256>>>(feat, bf);         // fe HGEMM (tensor cores) + mean
    k_initA<<<dim3(8, 8), 256>>>(W_hid, W_cell);  // init GEMM, split-K
    k_init2<<<NB, 256>>>(b_hid, b_cell);

    // entire 31-step decoder loop in ONE persistent kernel
    k_loop<<<NBLK, 256>>>(Wh, bh, We, be, b_gate, emb, tok,
                          b_ih, b_hh, b_head, out, out_att);
}